// round 9
// baseline (speedup 1.0000x reference)
#include <cuda_runtime.h>
#include <cuda_bf16.h>
#include <math_constants.h>
#include <cstdint>

#define BB   8
#define CIN  512
#define NN   4096
#define DDIM 256
#define KKE  2048
#define CAP  16
#define C0_BOUND 1.8e-2f

// ---- scratch (device globals; no allocation allowed) ----
__device__ float g_ze[BB * DDIM * NN];                 // (B, D, N) conv output
__device__ float g_zet[BB * NN * DDIM];                // ze fp32 transposed [b][n][d]
__device__ float g_esq[KKE];                           // ||e_k||^2
__device__ float g_enorm[KKE];                         // ||e_k||
__device__ float g_znorm[BB * NN];                     // ||ze_n||
__device__ int   g_minidx[BB * NN];                    // argmin indices
__device__ float g_zsum[KKE * DDIM];                   // segment sums
__device__ float g_nsum[KKE];                          // segment counts
__device__ __nv_bfloat16 g_embb[KKE * DDIM];           // emb high bf16 plane
__device__ __nv_bfloat16 g_zeb[BB * NN * DDIM];        // ze high plane, transposed
__device__ unsigned int g_cand[(size_t)BB * NN * CAP]; // candidate lists
__device__ unsigned int g_ccnt[BB * NN];               // candidate counts

__device__ __forceinline__ uint32_t smem_u32(const void* p) {
    uint32_t a;
    asm("{ .reg .u64 t; cvta.to.shared.u64 t, %1; cvt.u32.u64 %0, t; }" : "=r"(a) : "l"(p));
    return a;
}
__device__ __forceinline__ void ldsm_x4(uint32_t& r0, uint32_t& r1, uint32_t& r2, uint32_t& r3,
                                        uint32_t addr) {
    asm volatile("ldmatrix.sync.aligned.m8n8.x4.shared.b16 {%0,%1,%2,%3}, [%4];"
                 : "=r"(r0), "=r"(r1), "=r"(r2), "=r"(r3) : "r"(addr));
}
__device__ __forceinline__ void mma16816(float* c, const uint32_t* a, const uint32_t* b) {
    asm volatile("mma.sync.aligned.m16n8k16.row.col.f32.bf16.bf16.f32 "
                 "{%0,%1,%2,%3}, {%4,%5,%6,%7}, {%8,%9}, {%0,%1,%2,%3};"
                 : "+f"(c[0]), "+f"(c[1]), "+f"(c[2]), "+f"(c[3])
                 : "r"(a[0]), "r"(a[1]), "r"(a[2]), "r"(a[3]), "r"(b[0]), "r"(b[1]));
}
__device__ __forceinline__ uint32_t orderable(float s) {
    uint32_t u = __float_as_uint(s);
    return (u & 0x80000000u) ? ~u : (u | 0x80000000u);
}

// ============================================================
// e_sq + e_norm: one warp per codebook row
// ============================================================
__global__ void esq_kernel(const float* __restrict__ emb) {
    int warp = (blockIdx.x * blockDim.x + threadIdx.x) >> 5;
    int lane = threadIdx.x & 31;
    if (warp >= KKE) return;
    const float* row = emb + (size_t)warp * DDIM;
    float s = 0.f;
#pragma unroll
    for (int i = lane; i < DDIM; i += 32) { float v = row[i]; s += v * v; }
#pragma unroll
    for (int off = 16; off; off >>= 1) s += __shfl_down_sync(0xffffffffu, s, off);
    if (lane == 0) { g_esq[warp] = s; g_enorm[warp] = sqrtf(s); }
}

// ============================================================
// GEMM1: ze[b,d,n] = sum_c W[d,c] * z[b,c,n]   (R3 version)
// ============================================================
__global__ void __launch_bounds__(256, 2) gemm1_kernel(
    const float* __restrict__ z, const float* __restrict__ W)
{
    __shared__ float Ws[16][68];
    __shared__ float Zs[16][128];

    const int n0 = blockIdx.x * 128;
    const int d0 = blockIdx.y * 64;
    const int b  = blockIdx.z;
    const int tid = threadIdx.x;
    const int tk = tid >> 4;
    const int tn = tid & 15;

    float acc[4][8];
#pragma unroll
    for (int i = 0; i < 4; i++)
#pragma unroll
        for (int j = 0; j < 8; j++) acc[i][j] = 0.f;

    for (int c0 = 0; c0 < CIN; c0 += 16) {
#pragma unroll
        for (int i = 0; i < 4; i++) {
            int lin = tid + 256 * i;
            int dl = lin >> 4, cc = lin & 15;
            Ws[cc][dl] = W[(size_t)(d0 + dl) * CIN + c0 + cc];
        }
#pragma unroll
        for (int i = 0; i < 8; i++) {
            int lin = tid + 256 * i;
            int cc = lin >> 7, nl = lin & 127;
            Zs[cc][nl] = z[((size_t)b * CIN + c0 + cc) * NN + n0 + nl];
        }
        __syncthreads();
#pragma unroll
        for (int cc = 0; cc < 16; cc++) {
            float4 av = *(const float4*)&Ws[cc][tk * 4];
            float4 b0 = *(const float4*)&Zs[cc][tn * 8];
            float4 b1 = *(const float4*)&Zs[cc][tn * 8 + 4];
            float a[4] = {av.x, av.y, av.z, av.w};
            float bv[8] = {b0.x, b0.y, b0.z, b0.w, b1.x, b1.y, b1.z, b1.w};
#pragma unroll
            for (int i = 0; i < 4; i++)
#pragma unroll
                for (int j = 0; j < 8; j++) acc[i][j] += a[i] * bv[j];
        }
        __syncthreads();
    }
#pragma unroll
    for (int i = 0; i < 4; i++) {
        int d = d0 + tk * 4 + i;
        float* dst = &g_ze[((size_t)b * DDIM + d) * NN + n0 + tn * 8];
        *(float4*)dst       = make_float4(acc[i][0], acc[i][1], acc[i][2], acc[i][3]);
        *(float4*)(dst + 4) = make_float4(acc[i][4], acc[i][5], acc[i][6], acc[i][7]);
    }
}

// ============================================================
// split kernels: high bf16 plane only
// ============================================================
__global__ void split_emb_kernel(const float* __restrict__ emb) {
    int i = blockIdx.x * blockDim.x + threadIdx.x;
    if (i >= KKE * DDIM) return;
    g_embb[i] = __float2bfloat16(emb[i]);
}

// transpose ze -> fp32 g_zet + bf16 high plane g_zeb
__global__ void split_ze_kernel() {
    __shared__ float tile[64][65];
    const int n0 = blockIdx.x * 64;
    const int d0 = blockIdx.y * 64;
    const int b  = blockIdx.z;
    const int tid = threadIdx.x;
#pragma unroll
    for (int i = 0; i < 16; i++) {
        int idx = tid + 256 * i;
        int r = idx >> 6, cc = idx & 63;
        tile[r][cc] = g_ze[((size_t)b * DDIM + d0 + r) * NN + n0 + cc];
    }
    __syncthreads();
#pragma unroll
    for (int i = 0; i < 16; i++) {
        int idx = tid + 256 * i;
        int nr = idx >> 6, dc = idx & 63;
        float x = tile[dc][nr];
        size_t base = ((size_t)b * NN + n0 + nr) * DDIM + d0 + dc;
        g_zeb[base] = __float2bfloat16(x);
        g_zet[base] = x;
    }
}

// ============================================================
// znorm: one warp per column, from g_zet
// ============================================================
__global__ void znorm_kernel() {
    const int wid = threadIdx.x >> 5;
    const int L = threadIdx.x & 31;
    const int n = blockIdx.x * 8 + wid;
    const int b = blockIdx.y;
    const size_t cidx = (size_t)b * NN + n;
    const float* zr = g_zet + cidx * DDIM;
    float s = 0.f;
    float4 v0 = *(const float4*)(zr + L * 8);
    float4 v1 = *(const float4*)(zr + L * 8 + 4);
    s = v0.x*v0.x + v0.y*v0.y + v0.z*v0.z + v0.w*v0.w
      + v1.x*v1.x + v1.y*v1.y + v1.z*v1.z + v1.w*v1.w;
#pragma unroll
    for (int off = 16; off; off >>= 1) s += __shfl_xor_sync(0xffffffffu, s, off);
    if (L == 0) g_znorm[cidx] = sqrtf(s);
}

// ============================================================
// Pass A: 1-term approximate score GEMM (hh only) + rigorous
// candidate collection. CTA: k streamed (16 tiles of 128),
// 64 n-cols resident, full d=256 tiles. 8 warps = 4(M) x 2(N).
// smem: A [128k][512B sw] 64KB | B [64n][512B sw] 32KB | ctrl.
// ============================================================
#define A_BYTES  65536
#define OFF_B    A_BYTES                 // 65536
#define OFF_CTRL (A_BYTES + 32768)       // 98304
#define SMEM_ARG (OFF_CTRL + 6144)       // 104448

__global__ void __launch_bounds__(256, 2) argmin_approx_kernel()
{
    extern __shared__ char smem[];
    char* As = smem;                 // [k_local 128][512B swizzled]
    char* Bs = smem + OFF_B;         // [n_local 64][512B swizzled]
    unsigned int* colthr  = (unsigned int*)(smem + OFF_CTRL);        // [64]
    unsigned int* cnt_s   = (unsigned int*)(smem + OFF_CTRL + 256);  // [64]
    float* znorm_s        = (float*)(smem + OFF_CTRL + 512);         // [64]
    float* esq_s          = (float*)(smem + OFF_CTRL + 768);         // [128]
    float* enorm_s        = (float*)(smem + OFF_CTRL + 1280);        // [128]
    unsigned int* cand_s  = (unsigned int*)(smem + OFF_CTRL + 1792); // [64*CAP]

    const int tid = threadIdx.x;
    const int wid = tid >> 5;
    const int L   = tid & 31;
    const int n0  = blockIdx.x * 64;
    const int b   = blockIdx.y;
    const int wM  = wid >> 1;        // 0..3
    const int wN  = wid & 1;         // 0..1

    const uint32_t As_u = smem_u32(As);
    const uint32_t Bs_u = smem_u32(Bs);

    if (tid < 64) {
        colthr[tid] = 0xFFFFFFFFu;
        cnt_s[tid] = 0u;
        znorm_s[tid] = g_znorm[(size_t)b * NN + n0 + tid];
    }

    // ---- load resident B plane: 64 rows x 32 granules ----
#pragma unroll 4
    for (int q = 0; q < 8; q++) {
        int i = tid + 256 * q;               // 0..2047
        int r = i >> 5, g = i & 31;
        uint4 v = *(const uint4*)&g_zeb[((size_t)b * NN + n0 + r) * DDIM + g * 8];
        *(uint4*)(Bs + r * 512 + ((g ^ (r & 7)) * 16)) = v;
    }

    // per-lane static LDSM address components (validated R6-R8)
    const int rowA_l = L & 15;
    const int kxA    = L >> 4;
    const int rowB_l = (L & 7) | ((L & 16) >> 1);
    const int kxB    = (L >> 3) & 1;

    for (int kt = 0; kt < 16; kt++) {
        const int k0 = kt * 128;

        __syncthreads();   // prior tile's LDSMs done / B ready first pass
        // ---- load A tile: 128 rows x 32 granules (full d) ----
#pragma unroll 4
        for (int q = 0; q < 16; q++) {
            int i = tid + 256 * q;           // 0..4095
            int r = i >> 5, g = i & 31;
            uint4 v = *(const uint4*)&g_embb[(size_t)(k0 + r) * DDIM + g * 8];
            *(uint4*)(As + r * 512 + ((g ^ (r & 7)) * 16)) = v;
        }
        if (tid < 128) {
            esq_s[tid] = g_esq[k0 + tid];
            enorm_s[tid] = g_enorm[k0 + tid];
        }
        __syncthreads();

        float acc[2][4][4];
#pragma unroll
        for (int m = 0; m < 2; m++)
#pragma unroll
            for (int j = 0; j < 4; j++)
#pragma unroll
                for (int r = 0; r < 4; r++) acc[m][j][r] = 0.f;

#pragma unroll
        for (int dc = 0; dc < 16; dc++) {
            uint32_t a[2][4], bfr[2][4];
            {
                int rA0 = wM * 32 + rowA_l;
                int gA  = dc * 2 + kxA;
                ldsm_x4(a[0][0], a[0][1], a[0][2], a[0][3],
                        As_u + rA0 * 512 + ((gA ^ (rA0 & 7)) * 16));
                int rA1 = rA0 + 16;
                ldsm_x4(a[1][0], a[1][1], a[1][2], a[1][3],
                        As_u + rA1 * 512 + ((gA ^ (rA1 & 7)) * 16));
                int rB0 = wN * 32 + rowB_l;
                int gB  = dc * 2 + kxB;
                ldsm_x4(bfr[0][0], bfr[0][1], bfr[0][2], bfr[0][3],
                        Bs_u + rB0 * 512 + ((gB ^ (rB0 & 7)) * 16));
                int rB1 = rB0 + 16;
                ldsm_x4(bfr[1][0], bfr[1][1], bfr[1][2], bfr[1][3],
                        Bs_u + rB1 * 512 + ((gB ^ (rB1 & 7)) * 16));
            }
#pragma unroll
            for (int m = 0; m < 2; m++) {
                mma16816(acc[m][0], a[m], &bfr[0][0]);
                mma16816(acc[m][1], a[m], &bfr[0][2]);
                mma16816(acc[m][2], a[m], &bfr[1][0]);
                mma16816(acc[m][3], a[m], &bfr[1][2]);
            }
        }

        // ---- epilogue Phase 1: per-column min of (s + E) ----
        float zn[8];
#pragma unroll
        for (int j = 0; j < 4; j++)
#pragma unroll
            for (int par = 0; par < 2; par++)
                zn[j * 2 + par] = znorm_s[wN * 32 + j * 8 + (L & 3) * 2 + par];

        uint32_t umin[8];
#pragma unroll
        for (int c = 0; c < 8; c++) umin[c] = 0xFFFFFFFFu;

#pragma unroll
        for (int m = 0; m < 2; m++) {
            const int kl0 = wM * 32 + m * 16 + (L >> 2);
            const int kl1 = kl0 + 8;
            const float e0 = esq_s[kl0], e1 = esq_s[kl1];
            const float en0 = C0_BOUND * enorm_s[kl0], en1 = C0_BOUND * enorm_s[kl1];
#pragma unroll
            for (int j = 0; j < 4; j++)
#pragma unroll
                for (int r = 0; r < 4; r++) {
                    const int kh = r >> 1, par = r & 1;
                    float s = fmaf(-2.f, acc[m][j][r], kh ? e1 : e0);
                    float E = (kh ? en1 : en0) * zn[j * 2 + par];
                    uint32_t u = orderable(s + E);
                    if (u < umin[j * 2 + par]) umin[j * 2 + par] = u;
                }
        }
#pragma unroll
        for (int c = 0; c < 8; c++) {
#pragma unroll
            for (int off = 4; off <= 16; off <<= 1) {
                uint32_t o = __shfl_xor_sync(0xffffffffu, umin[c], off);
                if (o < umin[c]) umin[c] = o;
            }
        }
        if (L < 4) {
#pragma unroll
            for (int c = 0; c < 8; c++)
                atomicMin(&colthr[wN * 32 + (c >> 1) * 8 + L * 2 + (c & 1)], umin[c]);
        }
        __syncthreads();

        // ---- epilogue Phase 2: collect candidates ----
#pragma unroll
        for (int m = 0; m < 2; m++) {
            const int kl0 = wM * 32 + m * 16 + (L >> 2);
            const int kl1 = kl0 + 8;
            const float e0 = esq_s[kl0], e1 = esq_s[kl1];
            const float en0 = C0_BOUND * enorm_s[kl0], en1 = C0_BOUND * enorm_s[kl1];
#pragma unroll
            for (int j = 0; j < 4; j++)
#pragma unroll
                for (int r = 0; r < 4; r++) {
                    const int kh = r >> 1, par = r & 1;
                    const int col = wN * 32 + j * 8 + (L & 3) * 2 + par;
                    float s = fmaf(-2.f, acc[m][j][r], kh ? e1 : e0);
                    float E = (kh ? en1 : en0) * zn[j * 2 + par];
                    if (orderable(s - E) <= colthr[col]) {
                        unsigned pos = atomicAdd(&cnt_s[col], 1u);
                        if (pos < CAP)
                            cand_s[col * CAP + pos] = (unsigned)(k0 + (kh ? kl1 : kl0));
                    }
                }
        }
    }
    __syncthreads();
    // ---- write candidate lists to global ----
    if (tid < 64) g_ccnt[(size_t)b * NN + n0 + tid] = cnt_s[tid];
#pragma unroll
    for (int q = 0; q < 4; q++) {
        int i = tid + 256 * q;                  // 0..1023
        int lc = i >> 4, slot = i & 15;
        g_cand[((size_t)b * NN + n0 + lc) * CAP + slot] = cand_s[i];
    }
}

// ============================================================
// Pass B: exact fp32 refinement. One warp per column.
// ============================================================
__global__ void refine_kernel(const float* __restrict__ emb) {
    const int wid = threadIdx.x >> 5;
    const int L = threadIdx.x & 31;
    const int n = blockIdx.x * 8 + wid;
    const int b = blockIdx.y;
    const size_t cidx = (size_t)b * NN + n;
    const float* zr = g_zet + cidx * DDIM;

    const float4 z0 = *(const float4*)(zr + L * 8);
    const float4 z1 = *(const float4*)(zr + L * 8 + 4);

    const unsigned cnt = g_ccnt[cidx];
    unsigned long long best = 0xFFFFFFFFFFFFFFFFull;

    if (cnt <= CAP) {
        for (unsigned i = 0; i < cnt; i++) {
            const unsigned k = g_cand[cidx * CAP + i];
            const float* er = emb + (size_t)k * DDIM;
            float4 e0 = *(const float4*)(er + L * 8);
            float4 e1 = *(const float4*)(er + L * 8 + 4);
            float d = e0.x*z0.x;
            d = fmaf(e0.y, z0.y, d); d = fmaf(e0.z, z0.z, d); d = fmaf(e0.w, z0.w, d);
            d = fmaf(e1.x, z1.x, d); d = fmaf(e1.y, z1.y, d);
            d = fmaf(e1.z, z1.z, d); d = fmaf(e1.w, z1.w, d);
#pragma unroll
            for (int off = 16; off; off >>= 1) d += __shfl_xor_sync(0xffffffffu, d, off);
            float s = fmaf(-2.f, d, g_esq[k]);
            unsigned long long pk = ((unsigned long long)orderable(s) << 32) | k;
            if (pk < best) best = pk;
        }
    } else {
        // overflow fallback: exact scan of all codes, lane-strided
        for (int k = L; k < KKE; k += 32) {
            const float* er = emb + (size_t)k * DDIM;
            float d = 0.f;
#pragma unroll 8
            for (int v = 0; v < 64; v++) {
                float4 e4 = *(const float4*)(er + v * 4);
                float4 z4 = *(const float4*)(zr + v * 4);
                d = fmaf(e4.x, z4.x, d); d = fmaf(e4.y, z4.y, d);
                d = fmaf(e4.z, z4.z, d); d = fmaf(e4.w, z4.w, d);
            }
            float s = fmaf(-2.f, d, g_esq[k]);
            unsigned long long pk = ((unsigned long long)orderable(s) << 32) | (unsigned)k;
            if (pk < best) best = pk;
        }
#pragma unroll
        for (int off = 16; off; off >>= 1) {
            unsigned long long o = __shfl_xor_sync(0xffffffffu, best, off);
            if (o < best) best = o;
        }
    }
    if (L == 0) g_minidx[cidx] = (int)(best & 0xFFFFFFFFull);
}

// ============================================================
// zero scatter buffers
// ============================================================
__global__ void zero_kernel() {
    int total = KKE * DDIM + KKE;
    for (int i = blockIdx.x * blockDim.x + threadIdx.x; i < total;
         i += gridDim.x * blockDim.x) {
        if (i < KKE * DDIM) g_zsum[i] = 0.f;
        else g_nsum[i - KKE * DDIM] = 0.f;
    }
}

// ============================================================
// gather zq -> out, scatter-add ze into z_sum / n_sum
// ============================================================
__global__ void gs_kernel(const float* __restrict__ emb, float* __restrict__ out)
{
    const int b = blockIdx.y;
    const int n = blockIdx.x * 32 + threadIdx.x;
    const int ty = threadIdx.y;
    const int idx = g_minidx[(size_t)b * NN + n];
#pragma unroll 4
    for (int d = ty; d < DDIM; d += 8) {
        size_t zoff = ((size_t)b * DDIM + d) * NN + n;
        float zev = g_ze[zoff];
        out[zoff] = emb[(size_t)idx * DDIM + d];
        atomicAdd(&g_zsum[(size_t)idx * DDIM + d], zev);
    }
    if (ty == 0) atomicAdd(&g_nsum[idx], 1.0f);
}

// ============================================================
// EMA finalize -> tail of d_out
// ============================================================
__global__ void ema_kernel(const float* __restrict__ ema_numer,
                           const float* __restrict__ ema_denom,
                           float* __restrict__ out)
{
    const size_t OUT_OFF = (size_t)BB * DDIM * NN;
    int i = blockIdx.x * blockDim.x + threadIdx.x;
    if (i < KKE * DDIM)
        out[OUT_OFF + i] = 0.99f * ema_numer[i] + 0.01f * g_zsum[i];
    if (i < KKE)
        out[OUT_OFF + (size_t)KKE * DDIM + i] = 0.99f * ema_denom[i] + 0.01f * g_nsum[i];
}

// ============================================================
extern "C" void kernel_launch(void* const* d_in, const int* in_sizes, int n_in,
                              void* d_out, int out_size)
{
    const float* z         = (const float*)d_in[0];
    const float* W         = (const float*)d_in[1];
    const float* emb       = (const float*)d_in[2];
    const float* ema_numer = (const float*)d_in[3];
    const float* ema_denom = (const float*)d_in[4];
    float* out = (float*)d_out;
    (void)in_sizes; (void)n_in; (void)out_size;

    cudaFuncSetAttribute(argmin_approx_kernel,
                         cudaFuncAttributeMaxDynamicSharedMemorySize, SMEM_ARG);

    // 1. codebook norms + bf16 high plane of emb
    esq_kernel<<<(KKE * 32 + 255) / 256, 256>>>(emb);
    split_emb_kernel<<<(KKE * DDIM + 255) / 256, 256>>>(emb);

    // 2. ze = W * z  (1x1 conv, fp32)
    {
        dim3 grid(NN / 128, DDIM / 64, BB);
        gemm1_kernel<<<grid, 256>>>(z, W);
    }

    // 3. transpose ze (fp32 + bf16 high plane)
    {
        dim3 grid(NN / 64, DDIM / 64, BB);
        split_ze_kernel<<<grid, 256>>>();
    }

    // 4. column norms
    {
        dim3 grid(NN / 8, BB);
        znorm_kernel<<<grid, 256>>>();
    }

    // 5. Pass A: 1-term approx GEMM + candidate collection
    {
        dim3 grid(NN / 64, BB);
        argmin_approx_kernel<<<grid, 256, SMEM_ARG>>>();
    }

    // 6. Pass B: exact refinement -> g_minidx
    {
        dim3 grid(NN / 8, BB);
        refine_kernel<<<grid, 256>>>(emb);
    }

    // 7. zero scatter buffers
    zero_kernel<<<512, 256>>>();

    // 8. gather zq + scatter EMA statistics
    {
        dim3 grid(NN / 32, BB);
        dim3 blk(32, 8);
        gs_kernel<<<grid, blk>>>(emb, out);
    }

    // 9. EMA blend
    ema_kernel<<<(KKE * DDIM + 255) / 256, 256>>>(ema_numer, ema_denom, out);
}

// round 10
// speedup vs baseline: 1.7727x; 1.7727x over previous
#include <cuda_runtime.h>
#include <cuda_bf16.h>
#include <math_constants.h>
#include <cstdint>

#define BB   8
#define CIN  512
#define NN   4096
#define DDIM 256
#define KKE  2048
#define CAP  16
#define C0_BOUND 1.5e-4f

// ---- scratch (device globals; no allocation allowed) ----
__device__ float g_ze[BB * DDIM * NN];                 // (B, D, N) conv output
__device__ float g_zet[BB * NN * DDIM];                // ze fp32 transposed [b][n][d]
__device__ float g_esq[KKE];                           // ||e_k||^2
__device__ float g_enorm[KKE];                         // ||e_k||
__device__ float g_znorm2[BB * NN];                    // ||ze_n||^2 (atomic accum)
__device__ int   g_minidx[BB * NN];                    // argmin indices
__device__ float g_zsum[KKE * DDIM];                   // segment sums
__device__ float g_nsum[KKE];                          // segment counts
__device__ __nv_bfloat16 g_embb[2u * KKE * DDIM];      // emb 2-plane bf16 split
__device__ __nv_bfloat16 g_zeb[2u * BB * NN * DDIM];   // ze 2-plane split+transposed
__device__ unsigned int g_cand[(size_t)BB * NN * CAP]; // candidate lists
__device__ unsigned int g_ccnt[BB * NN];               // candidate counts

__device__ __forceinline__ uint32_t smem_u32(const void* p) {
    uint32_t a;
    asm("{ .reg .u64 t; cvta.to.shared.u64 t, %1; cvt.u32.u64 %0, t; }" : "=r"(a) : "l"(p));
    return a;
}
__device__ __forceinline__ void ldsm_x4(uint32_t& r0, uint32_t& r1, uint32_t& r2, uint32_t& r3,
                                        uint32_t addr) {
    asm volatile("ldmatrix.sync.aligned.m8n8.x4.shared.b16 {%0,%1,%2,%3}, [%4];"
                 : "=r"(r0), "=r"(r1), "=r"(r2), "=r"(r3) : "r"(addr));
}
__device__ __forceinline__ void mma16816(float* c, const uint32_t* a, const uint32_t* b) {
    asm volatile("mma.sync.aligned.m16n8k16.row.col.f32.bf16.bf16.f32 "
                 "{%0,%1,%2,%3}, {%4,%5,%6,%7}, {%8,%9}, {%0,%1,%2,%3};"
                 : "+f"(c[0]), "+f"(c[1]), "+f"(c[2]), "+f"(c[3])
                 : "r"(a[0]), "r"(a[1]), "r"(a[2]), "r"(a[3]), "r"(b[0]), "r"(b[1]));
}
__device__ __forceinline__ uint32_t orderable(float s) {
    uint32_t u = __float_as_uint(s);
    return (u & 0x80000000u) ? ~u : (u | 0x80000000u);
}
__device__ __forceinline__ void cp_async16(uint32_t smem_addr, const void* gptr) {
    asm volatile("cp.async.cg.shared.global [%0], [%1], 16;"
                 :: "r"(smem_addr), "l"(gptr) : "memory");
}
#define CP_COMMIT() asm volatile("cp.async.commit_group;" ::: "memory")
#define CP_WAIT1()  asm volatile("cp.async.wait_group 1;" ::: "memory")

// ============================================================
// e_sq + e_norm: one warp per codebook row
// ============================================================
__global__ void esq_kernel(const float* __restrict__ emb) {
    int warp = (blockIdx.x * blockDim.x + threadIdx.x) >> 5;
    int lane = threadIdx.x & 31;
    if (warp >= KKE) return;
    const float* row = emb + (size_t)warp * DDIM;
    float s = 0.f;
#pragma unroll
    for (int i = lane; i < DDIM; i += 32) { float v = row[i]; s += v * v; }
#pragma unroll
    for (int off = 16; off; off >>= 1) s += __shfl_down_sync(0xffffffffu, s, off);
    if (lane == 0) { g_esq[warp] = s; g_enorm[warp] = sqrtf(s); }
}

// ============================================================
// 2-plane bf16 split helper
// ============================================================
__device__ __forceinline__ void split2(float x, __nv_bfloat16& h, __nv_bfloat16& m) {
    h = __float2bfloat16(x);
    m = __float2bfloat16(x - __bfloat162float(h));
}

// split emb into 2 planes; also zero g_znorm2 for this launch (graph replay)
__global__ void split_emb_kernel(const float* __restrict__ emb) {
    int i = blockIdx.x * blockDim.x + threadIdx.x;
    if (i >= KKE * DDIM) return;
    __nv_bfloat16 h, m;
    split2(emb[i], h, m);
    g_embb[i] = h;
    g_embb[(size_t)KKE * DDIM + i] = m;
    if (i < BB * NN) g_znorm2[i] = 0.f;
}

// ============================================================
// GEMM1 (fused): ze = W*z, plus transposed fp32 g_zet, bf16
// planes g_zeb, and per-column ||ze||^2 partial accumulation.
// block tile: 64 (d) x 128 (n), K-chunk 16 over CIN.
// ============================================================
__global__ void __launch_bounds__(256, 2) gemm1_kernel(
    const float* __restrict__ z, const float* __restrict__ W)
{
    __shared__ float Ws[16][68];
    __shared__ float Zs[16][128];
    __shared__ float T[64][129];   // transpose staging

    const int n0 = blockIdx.x * 128;
    const int d0 = blockIdx.y * 64;
    const int b  = blockIdx.z;
    const int tid = threadIdx.x;
    const int tk = tid >> 4;
    const int tn = tid & 15;

    float acc[4][8];
#pragma unroll
    for (int i = 0; i < 4; i++)
#pragma unroll
        for (int j = 0; j < 8; j++) acc[i][j] = 0.f;

    for (int c0 = 0; c0 < CIN; c0 += 16) {
#pragma unroll
        for (int i = 0; i < 4; i++) {
            int lin = tid + 256 * i;
            int dl = lin >> 4, cc = lin & 15;
            Ws[cc][dl] = W[(size_t)(d0 + dl) * CIN + c0 + cc];
        }
#pragma unroll
        for (int i = 0; i < 8; i++) {
            int lin = tid + 256 * i;
            int cc = lin >> 7, nl = lin & 127;
            Zs[cc][nl] = z[((size_t)b * CIN + c0 + cc) * NN + n0 + nl];
        }
        __syncthreads();
#pragma unroll
        for (int cc = 0; cc < 16; cc++) {
            float4 av = *(const float4*)&Ws[cc][tk * 4];
            float4 b0 = *(const float4*)&Zs[cc][tn * 8];
            float4 b1 = *(const float4*)&Zs[cc][tn * 8 + 4];
            float a[4] = {av.x, av.y, av.z, av.w};
            float bv[8] = {b0.x, b0.y, b0.z, b0.w, b1.x, b1.y, b1.z, b1.w};
#pragma unroll
            for (int i = 0; i < 4; i++)
#pragma unroll
                for (int j = 0; j < 8; j++) acc[i][j] += a[i] * bv[j];
        }
        __syncthreads();
    }
    // ---- original layout writes (for gs_kernel) ----
#pragma unroll
    for (int i = 0; i < 4; i++) {
        int d = d0 + tk * 4 + i;
        float* dst = &g_ze[((size_t)b * DDIM + d) * NN + n0 + tn * 8];
        *(float4*)dst       = make_float4(acc[i][0], acc[i][1], acc[i][2], acc[i][3]);
        *(float4*)(dst + 4) = make_float4(acc[i][4], acc[i][5], acc[i][6], acc[i][7]);
    }
    // ---- stage transpose ----
#pragma unroll
    for (int i = 0; i < 4; i++)
#pragma unroll
        for (int j = 0; j < 8; j++)
            T[tk * 4 + i][tn * 8 + j] = acc[i][j];
    __syncthreads();
    // ---- transposed outputs: each thread = half an n-row (32 d's) ----
    {
        const int nl  = tid >> 1;
        const int dof = (tid & 1) * 32;
        const size_t ZP = (size_t)BB * NN * DDIM;
        const size_t base = ((size_t)b * NN + n0 + nl) * DDIM + d0 + dof;
        float s2 = 0.f;
        uint32_t hq[4], mq[4];
#pragma unroll
        for (int u8 = 0; u8 < 8; u8++) {
            float4 f = make_float4(T[dof + u8 * 4 + 0][nl], T[dof + u8 * 4 + 1][nl],
                                   T[dof + u8 * 4 + 2][nl], T[dof + u8 * 4 + 3][nl]);
            *(float4*)&g_zet[base + u8 * 4] = f;
            s2 = fmaf(f.x, f.x, s2); s2 = fmaf(f.y, f.y, s2);
            s2 = fmaf(f.z, f.z, s2); s2 = fmaf(f.w, f.w, s2);
            __nv_bfloat16 h0, m0, h1, m1, h2, m2, h3, m3;
            split2(f.x, h0, m0); split2(f.y, h1, m1);
            split2(f.z, h2, m2); split2(f.w, h3, m3);
            int q = (u8 & 1) * 2;
            hq[q]     = (uint32_t)__bfloat16_as_ushort(h0) | ((uint32_t)__bfloat16_as_ushort(h1) << 16);
            hq[q + 1] = (uint32_t)__bfloat16_as_ushort(h2) | ((uint32_t)__bfloat16_as_ushort(h3) << 16);
            mq[q]     = (uint32_t)__bfloat16_as_ushort(m0) | ((uint32_t)__bfloat16_as_ushort(m1) << 16);
            mq[q + 1] = (uint32_t)__bfloat16_as_ushort(m2) | ((uint32_t)__bfloat16_as_ushort(m3) << 16);
            if (u8 & 1) {
                int e0 = (u8 >> 1) * 8;
                *(uint4*)&g_zeb[base + e0]      = make_uint4(hq[0], hq[1], hq[2], hq[3]);
                *(uint4*)&g_zeb[ZP + base + e0] = make_uint4(mq[0], mq[1], mq[2], mq[3]);
            }
        }
        s2 += __shfl_xor_sync(0xffffffffu, s2, 1);
        if ((tid & 1) == 0)
            atomicAdd(&g_znorm2[(size_t)b * NN + n0 + nl], s2);
    }
}

// ============================================================
// Pass A: 3-term approximate score GEMM (hh+hm+mh) + rigorous
// candidate collection. cp.async double-buffered A tiles.
// CTA: k streamed (16 tiles of 128, 2 d-chunks), 64 n-cols
// resident. 8 warps = 4(M) x 2(N); warp tile 32k x 32n.
// ============================================================
#define ABUF     65536                  // one A stage: 2 planes x 128r x 256B
#define OFF_B    (2 * ABUF)             // 131072
#define OFF_CTRL (OFF_B + 65536)        // 196608
#define SMEM_ARG (OFF_CTRL + 6144)      // 202752

__global__ void __launch_bounds__(256, 1) argmin_approx_kernel()
{
    extern __shared__ char smem[];
    char* Bs = smem + OFF_B;         // 2 planes x [n_local 64][512B swizzled]
    unsigned int* colthr  = (unsigned int*)(smem + OFF_CTRL);        // [64]
    unsigned int* cnt_s   = (unsigned int*)(smem + OFF_CTRL + 256);  // [64]
    float* znorm_s        = (float*)(smem + OFF_CTRL + 512);         // [64]
    float* esq_s          = (float*)(smem + OFF_CTRL + 768);         // [128]
    float* enorm_s        = (float*)(smem + OFF_CTRL + 1280);        // [128]
    unsigned int* cand_s  = (unsigned int*)(smem + OFF_CTRL + 1792); // [64*CAP]

    const int tid = threadIdx.x;
    const int wid = tid >> 5;
    const int L   = tid & 31;
    const int n0  = blockIdx.x * 64;
    const int b   = blockIdx.y;
    const int wM  = wid >> 1;        // 0..3
    const int wN  = wid & 1;         // 0..1

    const uint32_t smem_base = smem_u32(smem);
    const uint32_t Bs_u = smem_base + OFF_B;
    const size_t ZP = (size_t)BB * NN * DDIM;

    if (tid < 64) {
        colthr[tid] = 0xFFFFFFFFu;
        cnt_s[tid] = 0u;
        znorm_s[tid] = sqrtf(g_znorm2[(size_t)b * NN + n0 + tid]);
    }

    // ---- load resident B planes (plain, full d, swizzled) ----
#pragma unroll 4
    for (int q = 0; q < 16; q++) {
        int i = tid + 256 * q;               // 0..4095
        int p = i >> 11;
        int rem = i & 2047;
        int r = rem >> 5, g = rem & 31;
        uint4 v = *(const uint4*)&g_zeb[p * ZP + ((size_t)b * NN + n0 + r) * DDIM + g * 8];
        *(uint4*)(Bs + p * 32768 + r * 512 + ((g ^ (r & 7)) * 16)) = v;
    }

    // per-lane static LDSM address components (validated R6-R9)
    const int rowA_l = L & 15;
    const int kxA    = L >> 4;
    const int rowB_l = (L & 7) | ((L & 16) >> 1);
    const int kxB    = (L >> 3) & 1;

    const int PA[3] = {0, 0, 1};
    const int PB[3] = {0, 1, 0};

    // ---- A stage prefetch helper (16 cp.asyncs / thread) ----
    auto load_A = [&](int s) {
        const int kt = s >> 1, dch = s & 1;
        const int k0 = kt * 128;
        const uint32_t dst0 = smem_base + (s & 1) * ABUF;
#pragma unroll 4
        for (int q = 0; q < 16; q++) {
            int i = tid + 256 * q;           // 0..4095
            int p = i >> 11;
            int rem = i & 2047;
            int r = rem >> 4, g = rem & 15;  // 128 rows x 16 granules
            const void* src = &g_embb[((size_t)p * KKE + k0 + r) * DDIM + dch * 128 + g * 8];
            cp_async16(dst0 + p * 32768 + r * 256 + ((g ^ (r & 7)) * 16), src);
        }
    };

    load_A(0);
    CP_COMMIT();

    float acc[2][4][4];

    for (int s = 0; s < 32; s++) {
        const int kt = s >> 1, dch = s & 1;
        const int k0 = kt * 128;

        if (s + 1 < 32) load_A(s + 1);
        CP_COMMIT();
        CP_WAIT1();
        if (dch == 0 && tid < 128) {
            esq_s[tid] = g_esq[k0 + tid];
            enorm_s[tid] = g_enorm[k0 + tid];
        }
        __syncthreads();

        if (dch == 0) {
#pragma unroll
            for (int m = 0; m < 2; m++)
#pragma unroll
                for (int j = 0; j < 4; j++)
#pragma unroll
                    for (int r = 0; r < 4; r++) acc[m][j][r] = 0.f;
        }

        const uint32_t AbufBase = smem_base + (s & 1) * ABUF;
#pragma unroll 1
        for (int t = 0; t < 3; t++) {
            const uint32_t Abase = AbufBase + PA[t] * 32768;
            const uint32_t Bbase = Bs_u + PB[t] * 32768;
#pragma unroll
            for (int dc = 0; dc < 8; dc++) {
                uint32_t a[2][4], bfr[2][4];
                {
                    int rA0 = wM * 32 + rowA_l;
                    int gA  = dc * 2 + kxA;
                    ldsm_x4(a[0][0], a[0][1], a[0][2], a[0][3],
                            Abase + rA0 * 256 + ((gA ^ (rA0 & 7)) * 16));
                    int rA1 = rA0 + 16;
                    ldsm_x4(a[1][0], a[1][1], a[1][2], a[1][3],
                            Abase + rA1 * 256 + ((gA ^ (rA1 & 7)) * 16));
                    int rB0 = wN * 32 + rowB_l;
                    int gB  = dch * 16 + dc * 2 + kxB;
                    ldsm_x4(bfr[0][0], bfr[0][1], bfr[0][2], bfr[0][3],
                            Bbase + rB0 * 512 + ((gB ^ (rB0 & 7)) * 16));
                    int rB1 = rB0 + 16;
                    ldsm_x4(bfr[1][0], bfr[1][1], bfr[1][2], bfr[1][3],
                            Bbase + rB1 * 512 + ((gB ^ (rB1 & 7)) * 16));
                }
#pragma unroll
                for (int m = 0; m < 2; m++) {
                    mma16816(acc[m][0], a[m], &bfr[0][0]);
                    mma16816(acc[m][1], a[m], &bfr[0][2]);
                    mma16816(acc[m][2], a[m], &bfr[1][0]);
                    mma16816(acc[m][3], a[m], &bfr[1][2]);
                }
            }
        }
        __syncthreads();   // all LDSMs done before this buffer is re-prefetched

        if (dch == 1) {
            // ---- epilogue Phase 1: s into acc; per-column min of (s + E) ----
            float zn[8];
#pragma unroll
            for (int j = 0; j < 4; j++)
#pragma unroll
                for (int par = 0; par < 2; par++)
                    zn[j * 2 + par] = znorm_s[wN * 32 + j * 8 + (L & 3) * 2 + par];

            uint32_t umin[8];
#pragma unroll
            for (int c = 0; c < 8; c++) umin[c] = 0xFFFFFFFFu;

#pragma unroll
            for (int m = 0; m < 2; m++) {
                const int kl0 = wM * 32 + m * 16 + (L >> 2);
                const int kl1 = kl0 + 8;
                const float e0 = esq_s[kl0], e1 = esq_s[kl1];
                const float en0 = C0_BOUND * enorm_s[kl0], en1 = C0_BOUND * enorm_s[kl1];
#pragma unroll
                for (int j = 0; j < 4; j++)
#pragma unroll
                    for (int r = 0; r < 4; r++) {
                        const int kh = r >> 1, par = r & 1;
                        float sc = fmaf(-2.f, acc[m][j][r], kh ? e1 : e0);
                        acc[m][j][r] = sc;   // cache score for phase 2
                        float E = (kh ? en1 : en0) * zn[j * 2 + par];
                        uint32_t u = orderable(sc + E);
                        if (u < umin[j * 2 + par]) umin[j * 2 + par] = u;
                    }
            }
#pragma unroll
            for (int c = 0; c < 8; c++) {
#pragma unroll
                for (int off = 4; off <= 16; off <<= 1) {
                    uint32_t o = __shfl_xor_sync(0xffffffffu, umin[c], off);
                    if (o < umin[c]) umin[c] = o;
                }
            }
            if (L < 4) {
#pragma unroll
                for (int c = 0; c < 8; c++)
                    atomicMin(&colthr[wN * 32 + (c >> 1) * 8 + L * 2 + (c & 1)], umin[c]);
            }
            __syncthreads();

            // ---- epilogue Phase 2: collect candidates ----
#pragma unroll
            for (int m = 0; m < 2; m++) {
                const int kl0 = wM * 32 + m * 16 + (L >> 2);
                const int kl1 = kl0 + 8;
                const float en0 = C0_BOUND * enorm_s[kl0], en1 = C0_BOUND * enorm_s[kl1];
#pragma unroll
                for (int j = 0; j < 4; j++)
#pragma unroll
                    for (int r = 0; r < 4; r++) {
                        const int kh = r >> 1, par = r & 1;
                        const int col = wN * 32 + j * 8 + (L & 3) * 2 + par;
                        float sc = acc[m][j][r];
                        float E = (kh ? en1 : en0) * zn[j * 2 + par];
                        if (orderable(sc - E) <= colthr[col]) {
                            unsigned pos = atomicAdd(&cnt_s[col], 1u);
                            if (pos < CAP)
                                cand_s[col * CAP + pos] = (unsigned)(k0 + (kh ? kl1 : kl0));
                        }
                    }
            }
        }
    }
    __syncthreads();
    // ---- write candidate lists to global ----
    if (tid < 64) g_ccnt[(size_t)b * NN + n0 + tid] = cnt_s[tid];
#pragma unroll
    for (int q = 0; q < 4; q++) {
        int i = tid + 256 * q;                  // 0..1023
        int lc = i >> 4, slot = i & 15;
        g_cand[((size_t)b * NN + n0 + lc) * CAP + slot] = cand_s[i];
    }
}

// ============================================================
// Pass B: exact fp32 refinement. One warp per column.
// ============================================================
__global__ void refine_kernel(const float* __restrict__ emb) {
    const int wid = threadIdx.x >> 5;
    const int L = threadIdx.x & 31;
    const int n = blockIdx.x * 8 + wid;
    const int b = blockIdx.y;
    const size_t cidx = (size_t)b * NN + n;
    const float* zr = g_zet + cidx * DDIM;

    const float4 z0 = *(const float4*)(zr + L * 8);
    const float4 z1 = *(const float4*)(zr + L * 8 + 4);

    const unsigned cnt = g_ccnt[cidx];
    unsigned long long best = 0xFFFFFFFFFFFFFFFFull;

    if (cnt <= CAP) {
        for (unsigned i = 0; i < cnt; i++) {
            const unsigned k = g_cand[cidx * CAP + i];
            const float* er = emb + (size_t)k * DDIM;
            float4 e0 = *(const float4*)(er + L * 8);
            float4 e1 = *(const float4*)(er + L * 8 + 4);
            float d = e0.x*z0.x;
            d = fmaf(e0.y, z0.y, d); d = fmaf(e0.z, z0.z, d); d = fmaf(e0.w, z0.w, d);
            d = fmaf(e1.x, z1.x, d); d = fmaf(e1.y, z1.y, d);
            d = fmaf(e1.z, z1.z, d); d = fmaf(e1.w, z1.w, d);
#pragma unroll
            for (int off = 16; off; off >>= 1) d += __shfl_xor_sync(0xffffffffu, d, off);
            float s = fmaf(-2.f, d, g_esq[k]);
            unsigned long long pk = ((unsigned long long)orderable(s) << 32) | k;
            if (pk < best) best = pk;
        }
    } else {
        // overflow fallback: exact scan of all codes, lane-strided
        for (int k = L; k < KKE; k += 32) {
            const float* er = emb + (size_t)k * DDIM;
            float d = 0.f;
#pragma unroll 8
            for (int v = 0; v < 64; v++) {
                float4 e4 = *(const float4*)(er + v * 4);
                float4 z4 = *(const float4*)(zr + v * 4);
                d = fmaf(e4.x, z4.x, d); d = fmaf(e4.y, z4.y, d);
                d = fmaf(e4.z, z4.z, d); d = fmaf(e4.w, z4.w, d);
            }
            float s = fmaf(-2.f, d, g_esq[k]);
            unsigned long long pk = ((unsigned long long)orderable(s) << 32) | (unsigned)k;
            if (pk < best) best = pk;
        }
#pragma unroll
        for (int off = 16; off; off >>= 1) {
            unsigned long long o = __shfl_xor_sync(0xffffffffu, best, off);
            if (o < best) best = o;
        }
    }
    if (L == 0) g_minidx[cidx] = (int)(best & 0xFFFFFFFFull);
}

// ============================================================
// zero scatter buffers
// ============================================================
__global__ void zero_kernel() {
    int total = KKE * DDIM + KKE;
    for (int i = blockIdx.x * blockDim.x + threadIdx.x; i < total;
         i += gridDim.x * blockDim.x) {
        if (i < KKE * DDIM) g_zsum[i] = 0.f;
        else g_nsum[i - KKE * DDIM] = 0.f;
    }
}

// ============================================================
// gather zq -> out, scatter-add ze into z_sum / n_sum
// ============================================================
__global__ void gs_kernel(const float* __restrict__ emb, float* __restrict__ out)
{
    const int b = blockIdx.y;
    const int n = blockIdx.x * 32 + threadIdx.x;
    const int ty = threadIdx.y;
    const int idx = g_minidx[(size_t)b * NN + n];
#pragma unroll 4
    for (int d = ty; d < DDIM; d += 8) {
        size_t zoff = ((size_t)b * DDIM + d) * NN + n;
        float zev = g_ze[zoff];
        out[zoff] = emb[(size_t)idx * DDIM + d];
        atomicAdd(&g_zsum[(size_t)idx * DDIM + d], zev);
    }
    if (ty == 0) atomicAdd(&g_nsum[idx], 1.0f);
}

// ============================================================
// EMA finalize -> tail of d_out
// ============================================================
__global__ void ema_kernel(const float* __restrict__ ema_numer,
                           const float* __restrict__ ema_denom,
                           float* __restrict__ out)
{
    const size_t OUT_OFF = (size_t)BB * DDIM * NN;
    int i = blockIdx.x * blockDim.x + threadIdx.x;
    if (i < KKE * DDIM)
        out[OUT_OFF + i] = 0.99f * ema_numer[i] + 0.01f * g_zsum[i];
    if (i < KKE)
        out[OUT_OFF + (size_t)KKE * DDIM + i] = 0.99f * ema_denom[i] + 0.01f * g_nsum[i];
}

// ============================================================
extern "C" void kernel_launch(void* const* d_in, const int* in_sizes, int n_in,
                              void* d_out, int out_size)
{
    const float* z         = (const float*)d_in[0];
    const float* W         = (const float*)d_in[1];
    const float* emb       = (const float*)d_in[2];
    const float* ema_numer = (const float*)d_in[3];
    const float* ema_denom = (const float*)d_in[4];
    float* out = (float*)d_out;
    (void)in_sizes; (void)n_in; (void)out_size;

    cudaFuncSetAttribute(argmin_approx_kernel,
                         cudaFuncAttributeMaxDynamicSharedMemorySize, SMEM_ARG);

    // 1. codebook norms + 2-plane bf16 split of emb (+ znorm2 zero)
    esq_kernel<<<(KKE * 32 + 255) / 256, 256>>>(emb);
    split_emb_kernel<<<(KKE * DDIM + 255) / 256, 256>>>(emb);

    // 2. fused GEMM1: ze + transposed fp32/bf16 planes + znorm2
    {
        dim3 grid(NN / 128, DDIM / 64, BB);
        gemm1_kernel<<<grid, 256>>>(z, W);
    }

    // 3. Pass A: 3-term approx GEMM + candidate collection
    {
        dim3 grid(NN / 64, BB);
        argmin_approx_kernel<<<grid, 256, SMEM_ARG>>>();
    }

    // 4. Pass B: exact refinement -> g_minidx
    {
        dim3 grid(NN / 8, BB);
        refine_kernel<<<grid, 256>>>(emb);
    }

    // 5. zero scatter buffers
    zero_kernel<<<512, 256>>>();

    // 6. gather zq + scatter EMA statistics
    {
        dim3 grid(NN / 32, BB);
        dim3 blk(32, 8);
        gs_kernel<<<grid, blk>>>(emb, out);
    }

    // 7. EMA blend
    ema_kernel<<<(KKE * DDIM + 255) / 256, 256>>>(ema_numer, ema_denom, out);
}

// round 11
// speedup vs baseline: 1.9364x; 1.0924x over previous
#include <cuda_runtime.h>
#include <cuda_bf16.h>
#include <math_constants.h>
#include <cstdint>

#define BB   8
#define CIN  512
#define NN   4096
#define DDIM 256
#define KKE  2048
#define CAP  16
#define C0_BOUND 1.5e-4f

// ---- scratch (device globals; no allocation allowed) ----
__device__ float g_ze[BB * DDIM * NN];                 // (B, D, N) conv output
__device__ float g_zet[BB * NN * DDIM];                // ze fp32 transposed [b][n][d]
__device__ float g_esq[KKE];                           // ||e_k||^2
__device__ float g_enorm[KKE];                         // ||e_k||
__device__ float g_znorm2[BB * NN];                    // ||ze_n||^2 (atomic accum)
__device__ int   g_minidx[BB * NN];                    // argmin indices
__device__ float g_zsum[KKE * DDIM];                   // segment sums
__device__ float g_nsum[KKE];                          // segment counts
__device__ __nv_bfloat16 g_embb[2u * KKE * DDIM];      // emb 2-plane bf16 split
__device__ __nv_bfloat16 g_zeb[2u * BB * NN * DDIM];   // ze 2-plane split+transposed
__device__ unsigned int g_cand[(size_t)BB * NN * CAP]; // candidate lists
__device__ unsigned int g_ccnt[BB * NN];               // candidate counts

__device__ __forceinline__ uint32_t smem_u32(const void* p) {
    uint32_t a;
    asm("{ .reg .u64 t; cvta.to.shared.u64 t, %1; cvt.u32.u64 %0, t; }" : "=r"(a) : "l"(p));
    return a;
}
__device__ __forceinline__ void ldsm_x4(uint32_t& r0, uint32_t& r1, uint32_t& r2, uint32_t& r3,
                                        uint32_t addr) {
    asm volatile("ldmatrix.sync.aligned.m8n8.x4.shared.b16 {%0,%1,%2,%3}, [%4];"
                 : "=r"(r0), "=r"(r1), "=r"(r2), "=r"(r3) : "r"(addr));
}
__device__ __forceinline__ void mma16816(float* c, const uint32_t* a, const uint32_t* b) {
    asm volatile("mma.sync.aligned.m16n8k16.row.col.f32.bf16.bf16.f32 "
                 "{%0,%1,%2,%3}, {%4,%5,%6,%7}, {%8,%9}, {%0,%1,%2,%3};"
                 : "+f"(c[0]), "+f"(c[1]), "+f"(c[2]), "+f"(c[3])
                 : "r"(a[0]), "r"(a[1]), "r"(a[2]), "r"(a[3]), "r"(b[0]), "r"(b[1]));
}
__device__ __forceinline__ uint32_t orderable(float s) {
    uint32_t u = __float_as_uint(s);
    return (u & 0x80000000u) ? ~u : (u | 0x80000000u);
}
__device__ __forceinline__ void cp_async16(uint32_t smem_addr, const void* gptr) {
    asm volatile("cp.async.cg.shared.global [%0], [%1], 16;"
                 :: "r"(smem_addr), "l"(gptr) : "memory");
}
#define CP_COMMIT() asm volatile("cp.async.commit_group;" ::: "memory")
#define CP_WAIT0()  asm volatile("cp.async.wait_group 0;" ::: "memory")

// ============================================================
// e_sq + e_norm: one warp per codebook row
// ============================================================
__global__ void esq_kernel(const float* __restrict__ emb) {
    int warp = (blockIdx.x * blockDim.x + threadIdx.x) >> 5;
    int lane = threadIdx.x & 31;
    if (warp >= KKE) return;
    const float* row = emb + (size_t)warp * DDIM;
    float s = 0.f;
#pragma unroll
    for (int i = lane; i < DDIM; i += 32) { float v = row[i]; s += v * v; }
#pragma unroll
    for (int off = 16; off; off >>= 1) s += __shfl_down_sync(0xffffffffu, s, off);
    if (lane == 0) { g_esq[warp] = s; g_enorm[warp] = sqrtf(s); }
}

// ============================================================
// 2-plane bf16 split helper
// ============================================================
__device__ __forceinline__ void split2(float x, __nv_bfloat16& h, __nv_bfloat16& m) {
    h = __float2bfloat16(x);
    m = __float2bfloat16(x - __bfloat162float(h));
}

// split emb into 2 planes; also zero g_znorm2 for this launch (graph replay)
__global__ void split_emb_kernel(const float* __restrict__ emb) {
    int i = blockIdx.x * blockDim.x + threadIdx.x;
    if (i >= KKE * DDIM) return;
    __nv_bfloat16 h, m;
    split2(emb[i], h, m);
    g_embb[i] = h;
    g_embb[(size_t)KKE * DDIM + i] = m;
    if (i < BB * NN) g_znorm2[i] = 0.f;
}

// ============================================================
// GEMM1 (fused): ze = W*z, plus transposed fp32 g_zet, bf16
// planes g_zeb, and per-column ||ze||^2 partial accumulation.
// ============================================================
__global__ void __launch_bounds__(256, 2) gemm1_kernel(
    const float* __restrict__ z, const float* __restrict__ W)
{
    __shared__ float Ws[16][68];
    __shared__ float Zs[16][128];
    __shared__ float T[64][129];   // transpose staging

    const int n0 = blockIdx.x * 128;
    const int d0 = blockIdx.y * 64;
    const int b  = blockIdx.z;
    const int tid = threadIdx.x;
    const int tk = tid >> 4;
    const int tn = tid & 15;

    float acc[4][8];
#pragma unroll
    for (int i = 0; i < 4; i++)
#pragma unroll
        for (int j = 0; j < 8; j++) acc[i][j] = 0.f;

    for (int c0 = 0; c0 < CIN; c0 += 16) {
#pragma unroll
        for (int i = 0; i < 4; i++) {
            int lin = tid + 256 * i;
            int dl = lin >> 4, cc = lin & 15;
            Ws[cc][dl] = W[(size_t)(d0 + dl) * CIN + c0 + cc];
        }
#pragma unroll
        for (int i = 0; i < 8; i++) {
            int lin = tid + 256 * i;
            int cc = lin >> 7, nl = lin & 127;
            Zs[cc][nl] = z[((size_t)b * CIN + c0 + cc) * NN + n0 + nl];
        }
        __syncthreads();
#pragma unroll
        for (int cc = 0; cc < 16; cc++) {
            float4 av = *(const float4*)&Ws[cc][tk * 4];
            float4 b0 = *(const float4*)&Zs[cc][tn * 8];
            float4 b1 = *(const float4*)&Zs[cc][tn * 8 + 4];
            float a[4] = {av.x, av.y, av.z, av.w};
            float bv[8] = {b0.x, b0.y, b0.z, b0.w, b1.x, b1.y, b1.z, b1.w};
#pragma unroll
            for (int i = 0; i < 4; i++)
#pragma unroll
                for (int j = 0; j < 8; j++) acc[i][j] += a[i] * bv[j];
        }
        __syncthreads();
    }
    // ---- original layout writes (for gs_kernel) ----
#pragma unroll
    for (int i = 0; i < 4; i++) {
        int d = d0 + tk * 4 + i;
        float* dst = &g_ze[((size_t)b * DDIM + d) * NN + n0 + tn * 8];
        *(float4*)dst       = make_float4(acc[i][0], acc[i][1], acc[i][2], acc[i][3]);
        *(float4*)(dst + 4) = make_float4(acc[i][4], acc[i][5], acc[i][6], acc[i][7]);
    }
    // ---- stage transpose ----
#pragma unroll
    for (int i = 0; i < 4; i++)
#pragma unroll
        for (int j = 0; j < 8; j++)
            T[tk * 4 + i][tn * 8 + j] = acc[i][j];
    __syncthreads();
    // ---- transposed outputs: each thread = half an n-row (32 d's) ----
    {
        const int nl  = tid >> 1;
        const int dof = (tid & 1) * 32;
        const size_t ZP = (size_t)BB * NN * DDIM;
        const size_t base = ((size_t)b * NN + n0 + nl) * DDIM + d0 + dof;
        float s2 = 0.f;
        uint32_t hq[4], mq[4];
#pragma unroll
        for (int u8 = 0; u8 < 8; u8++) {
            float4 f = make_float4(T[dof + u8 * 4 + 0][nl], T[dof + u8 * 4 + 1][nl],
                                   T[dof + u8 * 4 + 2][nl], T[dof + u8 * 4 + 3][nl]);
            *(float4*)&g_zet[base + u8 * 4] = f;
            s2 = fmaf(f.x, f.x, s2); s2 = fmaf(f.y, f.y, s2);
            s2 = fmaf(f.z, f.z, s2); s2 = fmaf(f.w, f.w, s2);
            __nv_bfloat16 h0, m0, h1, m1, h2, m2, h3, m3;
            split2(f.x, h0, m0); split2(f.y, h1, m1);
            split2(f.z, h2, m2); split2(f.w, h3, m3);
            int q = (u8 & 1) * 2;
            hq[q]     = (uint32_t)__bfloat16_as_ushort(h0) | ((uint32_t)__bfloat16_as_ushort(h1) << 16);
            hq[q + 1] = (uint32_t)__bfloat16_as_ushort(h2) | ((uint32_t)__bfloat16_as_ushort(h3) << 16);
            mq[q]     = (uint32_t)__bfloat16_as_ushort(m0) | ((uint32_t)__bfloat16_as_ushort(m1) << 16);
            mq[q + 1] = (uint32_t)__bfloat16_as_ushort(m2) | ((uint32_t)__bfloat16_as_ushort(m3) << 16);
            if (u8 & 1) {
                int e0 = (u8 >> 1) * 8;
                *(uint4*)&g_zeb[base + e0]      = make_uint4(hq[0], hq[1], hq[2], hq[3]);
                *(uint4*)&g_zeb[ZP + base + e0] = make_uint4(mq[0], mq[1], mq[2], mq[3]);
            }
        }
        s2 += __shfl_xor_sync(0xffffffffu, s2, 1);
        if ((tid & 1) == 0)
            atomicAdd(&g_znorm2[(size_t)b * NN + n0 + nl], s2);
    }
}

// ============================================================
// Pass A: 3-term approximate score GEMM (hh+hm+mh) + rigorous
// candidate collection. Single-buffered cp.async A stages
// (d-chunk 64) -> 102 KB smem -> 2 CTAs/SM for latency hiding.
// CTA: k streamed (16 tiles of 128, 4 d-chunks), 64 n-cols
// resident. 8 warps = 4(M) x 2(N); warp tile 32k x 32n.
// ============================================================
#define ABUF     32768                  // one A stage: 2 planes x 128r x 128B
#define OFF_B    ABUF                   // 32768
#define OFF_CTRL (OFF_B + 65536)        // 98304
#define SMEM_ARG (OFF_CTRL + 6144)      // 104448

__global__ void __launch_bounds__(256, 2) argmin_approx_kernel()
{
    extern __shared__ char smem[];
    char* Bs = smem + OFF_B;         // 2 planes x [n_local 64][512B swizzled]
    unsigned int* colthr  = (unsigned int*)(smem + OFF_CTRL);        // [64]
    unsigned int* cnt_s   = (unsigned int*)(smem + OFF_CTRL + 256);  // [64]
    float* znorm_s        = (float*)(smem + OFF_CTRL + 512);         // [64]
    float* esq_s          = (float*)(smem + OFF_CTRL + 768);         // [128]
    float* enorm_s        = (float*)(smem + OFF_CTRL + 1280);        // [128]
    unsigned int* cand_s  = (unsigned int*)(smem + OFF_CTRL + 1792); // [64*CAP]

    const int tid = threadIdx.x;
    const int wid = tid >> 5;
    const int L   = tid & 31;
    const int n0  = blockIdx.x * 64;
    const int b   = blockIdx.y;
    const int wM  = wid >> 1;        // 0..3
    const int wN  = wid & 1;         // 0..1

    const uint32_t smem_base = smem_u32(smem);
    const uint32_t Bs_u = smem_base + OFF_B;
    const size_t ZP = (size_t)BB * NN * DDIM;

    if (tid < 64) {
        colthr[tid] = 0xFFFFFFFFu;
        cnt_s[tid] = 0u;
        znorm_s[tid] = sqrtf(g_znorm2[(size_t)b * NN + n0 + tid]);
    }

    // ---- load resident B planes (plain, full d, swizzled) ----
#pragma unroll 4
    for (int q = 0; q < 16; q++) {
        int i = tid + 256 * q;               // 0..4095
        int p = i >> 11;
        int rem = i & 2047;
        int r = rem >> 5, g = rem & 31;
        uint4 v = *(const uint4*)&g_zeb[p * ZP + ((size_t)b * NN + n0 + r) * DDIM + g * 8];
        *(uint4*)(Bs + p * 32768 + r * 512 + ((g ^ (r & 7)) * 16)) = v;
    }

    // per-lane static LDSM address components (validated R6-R10)
    const int rowA_l = L & 15;
    const int kxA    = L >> 4;
    const int rowB_l = (L & 7) | ((L & 16) >> 1);
    const int kxB    = (L >> 3) & 1;

    const int PA[3] = {0, 0, 1};
    const int PB[3] = {0, 1, 0};

    float acc[2][4][4];

    // 64 stages: 16 k-tiles x 4 d-chunks of 64
    for (int s = 0; s < 64; s++) {
        const int kt = s >> 2, dch = s & 3;
        const int k0 = kt * 128;

        __syncthreads();   // prior stage's LDSMs done before A overwrite
        // ---- cp.async A d-chunk: 2 planes x 128 rows x 128B ----
#pragma unroll 4
        for (int q = 0; q < 8; q++) {
            int i = tid + 256 * q;           // 0..2047
            int p = i >> 10;
            int rem = i & 1023;
            int r = rem >> 3, g = rem & 7;   // 128 rows x 8 granules
            const void* src = &g_embb[((size_t)p * KKE + k0 + r) * DDIM + dch * 64 + g * 8];
            cp_async16(smem_base + p * 16384 + r * 128 + ((g ^ (r & 7)) * 16), src);
        }
        CP_COMMIT();
        if (dch == 0 && tid < 128) {
            esq_s[tid] = g_esq[k0 + tid];
            enorm_s[tid] = g_enorm[k0 + tid];
        }
        CP_WAIT0();
        __syncthreads();

        if (dch == 0) {
#pragma unroll
            for (int m = 0; m < 2; m++)
#pragma unroll
                for (int j = 0; j < 4; j++)
#pragma unroll
                    for (int r = 0; r < 4; r++) acc[m][j][r] = 0.f;
        }

#pragma unroll 1
        for (int t = 0; t < 3; t++) {
            const uint32_t Abase = smem_base + PA[t] * 16384;
            const uint32_t Bbase = Bs_u + PB[t] * 32768;
#pragma unroll
            for (int dc = 0; dc < 4; dc++) {
                uint32_t a[2][4], bfr[2][4];
                {
                    int rA0 = wM * 32 + rowA_l;
                    int gA  = dc * 2 + kxA;
                    ldsm_x4(a[0][0], a[0][1], a[0][2], a[0][3],
                            Abase + rA0 * 128 + ((gA ^ (rA0 & 7)) * 16));
                    int rA1 = rA0 + 16;
                    ldsm_x4(a[1][0], a[1][1], a[1][2], a[1][3],
                            Abase + rA1 * 128 + ((gA ^ (rA1 & 7)) * 16));
                    int rB0 = wN * 32 + rowB_l;
                    int gB  = dch * 8 + dc * 2 + kxB;
                    ldsm_x4(bfr[0][0], bfr[0][1], bfr[0][2], bfr[0][3],
                            Bbase + rB0 * 512 + ((gB ^ (rB0 & 7)) * 16));
                    int rB1 = rB0 + 16;
                    ldsm_x4(bfr[1][0], bfr[1][1], bfr[1][2], bfr[1][3],
                            Bbase + rB1 * 512 + ((gB ^ (rB1 & 7)) * 16));
                }
#pragma unroll
                for (int m = 0; m < 2; m++) {
                    mma16816(acc[m][0], a[m], &bfr[0][0]);
                    mma16816(acc[m][1], a[m], &bfr[0][2]);
                    mma16816(acc[m][2], a[m], &bfr[1][0]);
                    mma16816(acc[m][3], a[m], &bfr[1][2]);
                }
            }
        }

        if (dch == 3) {
            // ---- epilogue Phase 1: score into acc; per-column min of (s + E) ----
            float zn[8];
#pragma unroll
            for (int j = 0; j < 4; j++)
#pragma unroll
                for (int par = 0; par < 2; par++)
                    zn[j * 2 + par] = znorm_s[wN * 32 + j * 8 + (L & 3) * 2 + par];

            uint32_t umin[8];
#pragma unroll
            for (int c = 0; c < 8; c++) umin[c] = 0xFFFFFFFFu;

#pragma unroll
            for (int m = 0; m < 2; m++) {
                const int kl0 = wM * 32 + m * 16 + (L >> 2);
                const int kl1 = kl0 + 8;
                const float e0 = esq_s[kl0], e1 = esq_s[kl1];
                const float en0 = C0_BOUND * enorm_s[kl0], en1 = C0_BOUND * enorm_s[kl1];
#pragma unroll
                for (int j = 0; j < 4; j++)
#pragma unroll
                    for (int r = 0; r < 4; r++) {
                        const int kh = r >> 1, par = r & 1;
                        float sc = fmaf(-2.f, acc[m][j][r], kh ? e1 : e0);
                        acc[m][j][r] = sc;   // cache score for phase 2
                        float E = (kh ? en1 : en0) * zn[j * 2 + par];
                        uint32_t u = orderable(sc + E);
                        if (u < umin[j * 2 + par]) umin[j * 2 + par] = u;
                    }
            }
#pragma unroll
            for (int c = 0; c < 8; c++) {
#pragma unroll
                for (int off = 4; off <= 16; off <<= 1) {
                    uint32_t o = __shfl_xor_sync(0xffffffffu, umin[c], off);
                    if (o < umin[c]) umin[c] = o;
                }
            }
            if (L < 4) {
#pragma unroll
                for (int c = 0; c < 8; c++)
                    atomicMin(&colthr[wN * 32 + (c >> 1) * 8 + L * 2 + (c & 1)], umin[c]);
            }
            __syncthreads();

            // ---- epilogue Phase 2: collect candidates ----
#pragma unroll
            for (int m = 0; m < 2; m++) {
                const int kl0 = wM * 32 + m * 16 + (L >> 2);
                const int kl1 = kl0 + 8;
                const float en0 = C0_BOUND * enorm_s[kl0], en1 = C0_BOUND * enorm_s[kl1];
#pragma unroll
                for (int j = 0; j < 4; j++)
#pragma unroll
                    for (int r = 0; r < 4; r++) {
                        const int kh = r >> 1, par = r & 1;
                        const int col = wN * 32 + j * 8 + (L & 3) * 2 + par;
                        float sc = acc[m][j][r];
                        float E = (kh ? en1 : en0) * zn[j * 2 + par];
                        if (orderable(sc - E) <= colthr[col]) {
                            unsigned pos = atomicAdd(&cnt_s[col], 1u);
                            if (pos < CAP)
                                cand_s[col * CAP + pos] = (unsigned)(k0 + (kh ? kl1 : kl0));
                        }
                    }
            }
        }
    }
    __syncthreads();
    // ---- write candidate lists to global ----
    if (tid < 64) g_ccnt[(size_t)b * NN + n0 + tid] = cnt_s[tid];
#pragma unroll
    for (int q = 0; q < 4; q++) {
        int i = tid + 256 * q;                  // 0..1023
        int lc = i >> 4, slot = i & 15;
        g_cand[((size_t)b * NN + n0 + lc) * CAP + slot] = cand_s[i];
    }
}

// ============================================================
// Pass B: exact fp32 refinement. One warp per column.
// ============================================================
__global__ void refine_kernel(const float* __restrict__ emb) {
    const int wid = threadIdx.x >> 5;
    const int L = threadIdx.x & 31;
    const int n = blockIdx.x * 8 + wid;
    const int b = blockIdx.y;
    const size_t cidx = (size_t)b * NN + n;
    const float* zr = g_zet + cidx * DDIM;

    const float4 z0 = *(const float4*)(zr + L * 8);
    const float4 z1 = *(const float4*)(zr + L * 8 + 4);

    const unsigned cnt = g_ccnt[cidx];
    unsigned long long best = 0xFFFFFFFFFFFFFFFFull;

    if (cnt <= CAP) {
        for (unsigned i = 0; i < cnt; i++) {
            const unsigned k = g_cand[cidx * CAP + i];
            const float* er = emb + (size_t)k * DDIM;
            float4 e0 = *(const float4*)(er + L * 8);
            float4 e1 = *(const float4*)(er + L * 8 + 4);
            float d = e0.x*z0.x;
            d = fmaf(e0.y, z0.y, d); d = fmaf(e0.z, z0.z, d); d = fmaf(e0.w, z0.w, d);
            d = fmaf(e1.x, z1.x, d); d = fmaf(e1.y, z1.y, d);
            d = fmaf(e1.z, z1.z, d); d = fmaf(e1.w, z1.w, d);
#pragma unroll
            for (int off = 16; off; off >>= 1) d += __shfl_xor_sync(0xffffffffu, d, off);
            float s = fmaf(-2.f, d, g_esq[k]);
            unsigned long long pk = ((unsigned long long)orderable(s) << 32) | k;
            if (pk < best) best = pk;
        }
    } else {
        // overflow fallback: exact scan of all codes, lane-strided
        for (int k = L; k < KKE; k += 32) {
            const float* er = emb + (size_t)k * DDIM;
            float d = 0.f;
#pragma unroll 8
            for (int v = 0; v < 64; v++) {
                float4 e4 = *(const float4*)(er + v * 4);
                float4 z4 = *(const float4*)(zr + v * 4);
                d = fmaf(e4.x, z4.x, d); d = fmaf(e4.y, z4.y, d);
                d = fmaf(e4.z, z4.z, d); d = fmaf(e4.w, z4.w, d);
            }
            float s = fmaf(-2.f, d, g_esq[k]);
            unsigned long long pk = ((unsigned long long)orderable(s) << 32) | (unsigned)k;
            if (pk < best) best = pk;
        }
#pragma unroll
        for (int off = 16; off; off >>= 1) {
            unsigned long long o = __shfl_xor_sync(0xffffffffu, best, off);
            if (o < best) best = o;
        }
    }
    if (L == 0) g_minidx[cidx] = (int)(best & 0xFFFFFFFFull);
}

// ============================================================
// zero scatter buffers
// ============================================================
__global__ void zero_kernel() {
    int total = KKE * DDIM + KKE;
    for (int i = blockIdx.x * blockDim.x + threadIdx.x; i < total;
         i += gridDim.x * blockDim.x) {
        if (i < KKE * DDIM) g_zsum[i] = 0.f;
        else g_nsum[i - KKE * DDIM] = 0.f;
    }
}

// ============================================================
// gather zq -> out, scatter-add ze into z_sum / n_sum
// ============================================================
__global__ void gs_kernel(const float* __restrict__ emb, float* __restrict__ out)
{
    const int b = blockIdx.y;
    const int n = blockIdx.x * 32 + threadIdx.x;
    const int ty = threadIdx.y;
    const int idx = g_minidx[(size_t)b * NN + n];
#pragma unroll 4
    for (int d = ty; d < DDIM; d += 8) {
        size_t zoff = ((size_t)b * DDIM + d) * NN + n;
        float zev = g_ze[zoff];
        out[zoff] = emb[(size_t)idx * DDIM + d];
        atomicAdd(&g_zsum[(size_t)idx * DDIM + d], zev);
    }
    if (ty == 0) atomicAdd(&g_nsum[idx], 1.0f);
}

// ============================================================
// EMA finalize -> tail of d_out
// ============================================================
__global__ void ema_kernel(const float* __restrict__ ema_numer,
                           const float* __restrict__ ema_denom,
                           float* __restrict__ out)
{
    const size_t OUT_OFF = (size_t)BB * DDIM * NN;
    int i = blockIdx.x * blockDim.x + threadIdx.x;
    if (i < KKE * DDIM)
        out[OUT_OFF + i] = 0.99f * ema_numer[i] + 0.01f * g_zsum[i];
    if (i < KKE)
        out[OUT_OFF + (size_t)KKE * DDIM + i] = 0.99f * ema_denom[i] + 0.01f * g_nsum[i];
}

// ============================================================
extern "C" void kernel_launch(void* const* d_in, const int* in_sizes, int n_in,
                              void* d_out, int out_size)
{
    const float* z         = (const float*)d_in[0];
    const float* W         = (const float*)d_in[1];
    const float* emb       = (const float*)d_in[2];
    const float* ema_numer = (const float*)d_in[3];
    const float* ema_denom = (const float*)d_in[4];
    float* out = (float*)d_out;
    (void)in_sizes; (void)n_in; (void)out_size;

    cudaFuncSetAttribute(argmin_approx_kernel,
                         cudaFuncAttributeMaxDynamicSharedMemorySize, SMEM_ARG);

    // 1. codebook norms + 2-plane bf16 split of emb (+ znorm2 zero)
    esq_kernel<<<(KKE * 32 + 255) / 256, 256>>>(emb);
    split_emb_kernel<<<(KKE * DDIM + 255) / 256, 256>>>(emb);

    // 2. fused GEMM1: ze + transposed fp32/bf16 planes + znorm2
    {
        dim3 grid(NN / 128, DDIM / 64, BB);
        gemm1_kernel<<<grid, 256>>>(z, W);
    }

    // 3. Pass A: 3-term approx GEMM + candidate collection
    {
        dim3 grid(NN / 64, BB);
        argmin_approx_kernel<<<grid, 256, SMEM_ARG>>>();
    }

    // 4. Pass B: exact refinement -> g_minidx
    {
        dim3 grid(NN / 8, BB);
        refine_kernel<<<grid, 256>>>(emb);
    }

    // 5. zero scatter buffers
    zero_kernel<<<512, 256>>>();

    // 6. gather zq + scatter EMA statistics
    {
        dim3 grid(NN / 32, BB);
        dim3 blk(32, 8);
        gs_kernel<<<grid, blk>>>(emb, out);
    }

    // 7. EMA blend
    ema_kernel<<<(KKE * DDIM + 255) / 256, 256>>>(ema_numer, ema_denom, out);
}

// round 12
// speedup vs baseline: 1.9605x; 1.0124x over previous
#include <cuda_runtime.h>
#include <cuda_bf16.h>
#include <math_constants.h>
#include <cstdint>

#define BB   8
#define CIN  512
#define NN   4096
#define DDIM 256
#define KKE  2048
#define CAP  16
#define C0_BOUND 1.5e-4f

// ---- scratch (device globals; no allocation allowed) ----
__device__ float g_zet[BB * NN * DDIM];                // ze fp32 transposed [b][n][d]
__device__ float g_esq[KKE];                           // ||e_k||^2
__device__ float g_enorm[KKE];                         // ||e_k||
__device__ float g_znorm2[BB * NN];                    // ||ze_n||^2 (atomic accum)
__device__ int   g_minidx[BB * NN];                    // argmin indices
__device__ float g_zsum[KKE * DDIM];                   // segment sums
__device__ float g_nsum[KKE];                          // segment counts
__device__ __nv_bfloat16 g_embb[2u * KKE * DDIM];      // emb 2-plane bf16 split
__device__ __nv_bfloat16 g_zeb[2u * BB * NN * DDIM];   // ze 2-plane split+transposed
__device__ unsigned int g_cand[(size_t)BB * NN * CAP]; // candidate lists
__device__ unsigned int g_ccnt[BB * NN];               // candidate counts

__device__ __forceinline__ uint32_t smem_u32(const void* p) {
    uint32_t a;
    asm("{ .reg .u64 t; cvta.to.shared.u64 t, %1; cvt.u32.u64 %0, t; }" : "=r"(a) : "l"(p));
    return a;
}
__device__ __forceinline__ void ldsm_x4(uint32_t& r0, uint32_t& r1, uint32_t& r2, uint32_t& r3,
                                        uint32_t addr) {
    asm volatile("ldmatrix.sync.aligned.m8n8.x4.shared.b16 {%0,%1,%2,%3}, [%4];"
                 : "=r"(r0), "=r"(r1), "=r"(r2), "=r"(r3) : "r"(addr));
}
__device__ __forceinline__ void mma16816(float* c, const uint32_t* a, const uint32_t* b) {
    asm volatile("mma.sync.aligned.m16n8k16.row.col.f32.bf16.bf16.f32 "
                 "{%0,%1,%2,%3}, {%4,%5,%6,%7}, {%8,%9}, {%0,%1,%2,%3};"
                 : "+f"(c[0]), "+f"(c[1]), "+f"(c[2]), "+f"(c[3])
                 : "r"(a[0]), "r"(a[1]), "r"(a[2]), "r"(a[3]), "r"(b[0]), "r"(b[1]));
}
__device__ __forceinline__ uint32_t orderable(float s) {
    uint32_t u = __float_as_uint(s);
    return (u & 0x80000000u) ? ~u : (u | 0x80000000u);
}
__device__ __forceinline__ void cp_async16(uint32_t smem_addr, const void* gptr) {
    asm volatile("cp.async.cg.shared.global [%0], [%1], 16;"
                 :: "r"(smem_addr), "l"(gptr) : "memory");
}
#define CP_COMMIT() asm volatile("cp.async.commit_group;" ::: "memory")
#define CP_WAIT0()  asm volatile("cp.async.wait_group 0;" ::: "memory")

// ============================================================
// e_sq + e_norm: one warp per codebook row
// ============================================================
__global__ void esq_kernel(const float* __restrict__ emb) {
    int warp = (blockIdx.x * blockDim.x + threadIdx.x) >> 5;
    int lane = threadIdx.x & 31;
    if (warp >= KKE) return;
    const float* row = emb + (size_t)warp * DDIM;
    float s = 0.f;
#pragma unroll
    for (int i = lane; i < DDIM; i += 32) { float v = row[i]; s += v * v; }
#pragma unroll
    for (int off = 16; off; off >>= 1) s += __shfl_down_sync(0xffffffffu, s, off);
    if (lane == 0) { g_esq[warp] = s; g_enorm[warp] = sqrtf(s); }
}

// ============================================================
// 2-plane bf16 split helper
// ============================================================
__device__ __forceinline__ void split2(float x, __nv_bfloat16& h, __nv_bfloat16& m) {
    h = __float2bfloat16(x);
    m = __float2bfloat16(x - __bfloat162float(h));
}

// split emb into 2 planes; also zero g_znorm2 for this launch (graph replay)
__global__ void split_emb_kernel(const float* __restrict__ emb) {
    int i = blockIdx.x * blockDim.x + threadIdx.x;
    if (i >= KKE * DDIM) return;
    __nv_bfloat16 h, m;
    split2(emb[i], h, m);
    g_embb[i] = h;
    g_embb[(size_t)KKE * DDIM + i] = m;
    if (i < BB * NN) g_znorm2[i] = 0.f;
}

// ============================================================
// GEMM1 (fused): ze = W*z -> transposed fp32 g_zet, bf16
// planes g_zeb, and per-column ||ze||^2 partial accumulation.
// (g_ze original-layout copy removed; gs reads g_zet.)
// ============================================================
__global__ void __launch_bounds__(256, 2) gemm1_kernel(
    const float* __restrict__ z, const float* __restrict__ W)
{
    __shared__ float Ws[16][68];
    __shared__ float Zs[16][128];
    __shared__ float T[64][129];   // transpose staging

    const int n0 = blockIdx.x * 128;
    const int d0 = blockIdx.y * 64;
    const int b  = blockIdx.z;
    const int tid = threadIdx.x;
    const int tk = tid >> 4;
    const int tn = tid & 15;

    float acc[4][8];
#pragma unroll
    for (int i = 0; i < 4; i++)
#pragma unroll
        for (int j = 0; j < 8; j++) acc[i][j] = 0.f;

    for (int c0 = 0; c0 < CIN; c0 += 16) {
#pragma unroll
        for (int i = 0; i < 4; i++) {
            int lin = tid + 256 * i;
            int dl = lin >> 4, cc = lin & 15;
            Ws[cc][dl] = W[(size_t)(d0 + dl) * CIN + c0 + cc];
        }
#pragma unroll
        for (int i = 0; i < 8; i++) {
            int lin = tid + 256 * i;
            int cc = lin >> 7, nl = lin & 127;
            Zs[cc][nl] = z[((size_t)b * CIN + c0 + cc) * NN + n0 + nl];
        }
        __syncthreads();
#pragma unroll
        for (int cc = 0; cc < 16; cc++) {
            float4 av = *(const float4*)&Ws[cc][tk * 4];
            float4 b0 = *(const float4*)&Zs[cc][tn * 8];
            float4 b1 = *(const float4*)&Zs[cc][tn * 8 + 4];
            float a[4] = {av.x, av.y, av.z, av.w};
            float bv[8] = {b0.x, b0.y, b0.z, b0.w, b1.x, b1.y, b1.z, b1.w};
#pragma unroll
            for (int i = 0; i < 4; i++)
#pragma unroll
                for (int j = 0; j < 8; j++) acc[i][j] += a[i] * bv[j];
        }
        __syncthreads();
    }
    // ---- stage transpose ----
#pragma unroll
    for (int i = 0; i < 4; i++)
#pragma unroll
        for (int j = 0; j < 8; j++)
            T[tk * 4 + i][tn * 8 + j] = acc[i][j];
    __syncthreads();
    // ---- transposed outputs: each thread = half an n-row (32 d's) ----
    {
        const int nl  = tid >> 1;
        const int dof = (tid & 1) * 32;
        const size_t ZP = (size_t)BB * NN * DDIM;
        const size_t base = ((size_t)b * NN + n0 + nl) * DDIM + d0 + dof;
        float s2 = 0.f;
        uint32_t hq[4], mq[4];
#pragma unroll
        for (int u8 = 0; u8 < 8; u8++) {
            float4 f = make_float4(T[dof + u8 * 4 + 0][nl], T[dof + u8 * 4 + 1][nl],
                                   T[dof + u8 * 4 + 2][nl], T[dof + u8 * 4 + 3][nl]);
            *(float4*)&g_zet[base + u8 * 4] = f;
            s2 = fmaf(f.x, f.x, s2); s2 = fmaf(f.y, f.y, s2);
            s2 = fmaf(f.z, f.z, s2); s2 = fmaf(f.w, f.w, s2);
            __nv_bfloat16 h0, m0, h1, m1, h2, m2, h3, m3;
            split2(f.x, h0, m0); split2(f.y, h1, m1);
            split2(f.z, h2, m2); split2(f.w, h3, m3);
            int q = (u8 & 1) * 2;
            hq[q]     = (uint32_t)__bfloat16_as_ushort(h0) | ((uint32_t)__bfloat16_as_ushort(h1) << 16);
            hq[q + 1] = (uint32_t)__bfloat16_as_ushort(h2) | ((uint32_t)__bfloat16_as_ushort(h3) << 16);
            mq[q]     = (uint32_t)__bfloat16_as_ushort(m0) | ((uint32_t)__bfloat16_as_ushort(m1) << 16);
            mq[q + 1] = (uint32_t)__bfloat16_as_ushort(m2) | ((uint32_t)__bfloat16_as_ushort(m3) << 16);
            if (u8 & 1) {
                int e0 = (u8 >> 1) * 8;
                *(uint4*)&g_zeb[base + e0]      = make_uint4(hq[0], hq[1], hq[2], hq[3]);
                *(uint4*)&g_zeb[ZP + base + e0] = make_uint4(mq[0], mq[1], mq[2], mq[3]);
            }
        }
        s2 += __shfl_xor_sync(0xffffffffu, s2, 1);
        if ((tid & 1) == 0)
            atomicAdd(&g_znorm2[(size_t)b * NN + n0 + nl], s2);
    }
}

// ============================================================
// Pass A: 3-term approximate score GEMM (hh+hm+mh) + rigorous
// candidate collection. Double-buffered cp.async stages where
// BOTH A (codes) and B (ze) d-chunks are streamed:
//   stage = 48KB (A 2x16KB + B 2x8KB), 2 buffers + ctrl = 102KB
//   -> 2 CTAs/SM AND full load/compute overlap, 1 barrier/stage.
// CTA: k streamed (16 tiles of 128, 4 d-chunks of 64), 64 n-cols.
// 8 warps = 4(M) x 2(N); warp tile 32k x 32n.
// ============================================================
#define STAGE_B  49152                  // A_h 16K | A_m 16K | B_h 8K | B_m 8K
#define OFF_CTRL (2 * STAGE_B)          // 98304
#define SMEM_ARG (OFF_CTRL + 6144)      // 104448

__global__ void __launch_bounds__(256, 2) argmin_approx_kernel()
{
    extern __shared__ char smem[];
    unsigned int* colthr  = (unsigned int*)(smem + OFF_CTRL);        // [64]
    unsigned int* cnt_s   = (unsigned int*)(smem + OFF_CTRL + 256);  // [64]
    float* znorm_s        = (float*)(smem + OFF_CTRL + 512);         // [64]
    float* esq_s          = (float*)(smem + OFF_CTRL + 768);         // [128]
    float* enorm_s        = (float*)(smem + OFF_CTRL + 1280);        // [128]
    unsigned int* cand_s  = (unsigned int*)(smem + OFF_CTRL + 1792); // [64*CAP]

    const int tid = threadIdx.x;
    const int wid = tid >> 5;
    const int L   = tid & 31;
    const int n0  = blockIdx.x * 64;
    const int b   = blockIdx.y;
    const int wM  = wid >> 1;        // 0..3
    const int wN  = wid & 1;         // 0..1

    const uint32_t smem_base = smem_u32(smem);
    const size_t ZP = (size_t)BB * NN * DDIM;

    if (tid < 64) {
        colthr[tid] = 0xFFFFFFFFu;
        cnt_s[tid] = 0u;
        znorm_s[tid] = sqrtf(g_znorm2[(size_t)b * NN + n0 + tid]);
    }

    // per-lane static LDSM address components (validated R6-R11)
    const int rowA_l = L & 15;
    const int kxA    = L >> 4;
    const int rowB_l = (L & 7) | ((L & 16) >> 1);
    const int kxB    = (L >> 3) & 1;

    const int PA[3] = {0, 0, 1};
    const int PB[3] = {0, 1, 0};

    // ---- stage prefetch: A chunk (2 planes 128r x 128B) + B chunk (2 planes 64r x 128B) ----
    auto load_stage = [&](int s) {
        const int kt = s >> 2, dch = s & 3;
        const int k0 = kt * 128;
        const uint32_t dst = smem_base + (s & 1) * STAGE_B;
#pragma unroll 4
        for (int q = 0; q < 8; q++) {          // A: 2048 granules
            int i = tid + 256 * q;
            int p = i >> 10;
            int rem = i & 1023;
            int r = rem >> 3, g = rem & 7;
            const void* src = &g_embb[((size_t)p * KKE + k0 + r) * DDIM + dch * 64 + g * 8];
            cp_async16(dst + p * 16384 + r * 128 + ((g ^ (r & 7)) * 16), src);
        }
#pragma unroll 4
        for (int q = 0; q < 4; q++) {          // B: 1024 granules
            int i = tid + 256 * q;
            int p = i >> 9;
            int rem = i & 511;
            int r = rem >> 3, g = rem & 7;
            const void* src = &g_zeb[p * ZP + ((size_t)b * NN + n0 + r) * DDIM + dch * 64 + g * 8];
            cp_async16(dst + 32768 + p * 8192 + r * 128 + ((g ^ (r & 7)) * 16), src);
        }
    };

    load_stage(0);
    CP_COMMIT();

    float acc[2][4][4];

    // 64 stages: 16 k-tiles x 4 d-chunks of 64
    for (int s = 0; s < 64; s++) {
        const int kt = s >> 2, dch = s & 3;
        const int k0 = kt * 128;

        CP_WAIT0();        // stage s data landed
        __syncthreads();   // publish stage s; all warps past compute(s-1)

        if (s + 1 < 64) { load_stage(s + 1); CP_COMMIT(); }
        if (dch == 0 && tid < 128) {
            esq_s[tid] = g_esq[k0 + tid];
            enorm_s[tid] = g_enorm[k0 + tid];
        }

        if (dch == 0) {
#pragma unroll
            for (int m = 0; m < 2; m++)
#pragma unroll
                for (int j = 0; j < 4; j++)
#pragma unroll
                    for (int r = 0; r < 4; r++) acc[m][j][r] = 0.f;
        }

        const uint32_t buf = smem_base + (s & 1) * STAGE_B;
#pragma unroll 1
        for (int t = 0; t < 3; t++) {
            const uint32_t Abase = buf + PA[t] * 16384;
            const uint32_t Bbase = buf + 32768 + PB[t] * 8192;
#pragma unroll
            for (int dc = 0; dc < 4; dc++) {
                uint32_t a[2][4], bfr[2][4];
                {
                    int rA0 = wM * 32 + rowA_l;
                    int gA  = dc * 2 + kxA;
                    ldsm_x4(a[0][0], a[0][1], a[0][2], a[0][3],
                            Abase + rA0 * 128 + ((gA ^ (rA0 & 7)) * 16));
                    int rA1 = rA0 + 16;
                    ldsm_x4(a[1][0], a[1][1], a[1][2], a[1][3],
                            Abase + rA1 * 128 + ((gA ^ (rA1 & 7)) * 16));
                    int rB0 = wN * 32 + rowB_l;
                    int gB  = dc * 2 + kxB;
                    ldsm_x4(bfr[0][0], bfr[0][1], bfr[0][2], bfr[0][3],
                            Bbase + rB0 * 128 + ((gB ^ (rB0 & 7)) * 16));
                    int rB1 = rB0 + 16;
                    ldsm_x4(bfr[1][0], bfr[1][1], bfr[1][2], bfr[1][3],
                            Bbase + rB1 * 128 + ((gB ^ (rB1 & 7)) * 16));
                }
#pragma unroll
                for (int m = 0; m < 2; m++) {
                    mma16816(acc[m][0], a[m], &bfr[0][0]);
                    mma16816(acc[m][1], a[m], &bfr[0][2]);
                    mma16816(acc[m][2], a[m], &bfr[1][0]);
                    mma16816(acc[m][3], a[m], &bfr[1][2]);
                }
            }
        }

        if (dch == 3) {
            // ---- epilogue Phase 1: score into acc; per-column min of (s + E) ----
            float zn[8];
#pragma unroll
            for (int j = 0; j < 4; j++)
#pragma unroll
                for (int par = 0; par < 2; par++)
                    zn[j * 2 + par] = znorm_s[wN * 32 + j * 8 + (L & 3) * 2 + par];

            uint32_t umin[8];
#pragma unroll
            for (int c = 0; c < 8; c++) umin[c] = 0xFFFFFFFFu;

#pragma unroll
            for (int m = 0; m < 2; m++) {
                const int kl0 = wM * 32 + m * 16 + (L >> 2);
                const int kl1 = kl0 + 8;
                const float e0 = esq_s[kl0], e1 = esq_s[kl1];
                const float en0 = C0_BOUND * enorm_s[kl0], en1 = C0_BOUND * enorm_s[kl1];
#pragma unroll
                for (int j = 0; j < 4; j++)
#pragma unroll
                    for (int r = 0; r < 4; r++) {
                        const int kh = r >> 1, par = r & 1;
                        float sc = fmaf(-2.f, acc[m][j][r], kh ? e1 : e0);
                        acc[m][j][r] = sc;   // cache score for phase 2
                        float E = (kh ? en1 : en0) * zn[j * 2 + par];
                        uint32_t u = orderable(sc + E);
                        if (u < umin[j * 2 + par]) umin[j * 2 + par] = u;
                    }
            }
#pragma unroll
            for (int c = 0; c < 8; c++) {
#pragma unroll
                for (int off = 4; off <= 16; off <<= 1) {
                    uint32_t o = __shfl_xor_sync(0xffffffffu, umin[c], off);
                    if (o < umin[c]) umin[c] = o;
                }
            }
            if (L < 4) {
#pragma unroll
                for (int c = 0; c < 8; c++)
                    atomicMin(&colthr[wN * 32 + (c >> 1) * 8 + L * 2 + (c & 1)], umin[c]);
            }
            __syncthreads();

            // ---- epilogue Phase 2: collect candidates ----
#pragma unroll
            for (int m = 0; m < 2; m++) {
                const int kl0 = wM * 32 + m * 16 + (L >> 2);
                const int kl1 = kl0 + 8;
                const float en0 = C0_BOUND * enorm_s[kl0], en1 = C0_BOUND * enorm_s[kl1];
#pragma unroll
                for (int j = 0; j < 4; j++)
#pragma unroll
                    for (int r = 0; r < 4; r++) {
                        const int kh = r >> 1, par = r & 1;
                        const int col = wN * 32 + j * 8 + (L & 3) * 2 + par;
                        float sc = acc[m][j][r];
                        float E = (kh ? en1 : en0) * zn[j * 2 + par];
                        if (orderable(sc - E) <= colthr[col]) {
                            unsigned pos = atomicAdd(&cnt_s[col], 1u);
                            if (pos < CAP)
                                cand_s[col * CAP + pos] = (unsigned)(k0 + (kh ? kl1 : kl0));
                        }
                    }
            }
        }
    }
    __syncthreads();
    // ---- write candidate lists to global ----
    if (tid < 64) g_ccnt[(size_t)b * NN + n0 + tid] = cnt_s[tid];
#pragma unroll
    for (int q = 0; q < 4; q++) {
        int i = tid + 256 * q;                  // 0..1023
        int lc = i >> 4, slot = i & 15;
        g_cand[((size_t)b * NN + n0 + lc) * CAP + slot] = cand_s[i];
    }
}

// ============================================================
// Pass B: exact fp32 refinement. One warp per column.
// ============================================================
__global__ void refine_kernel(const float* __restrict__ emb) {
    const int wid = threadIdx.x >> 5;
    const int L = threadIdx.x & 31;
    const int n = blockIdx.x * 8 + wid;
    const int b = blockIdx.y;
    const size_t cidx = (size_t)b * NN + n;
    const float* zr = g_zet + cidx * DDIM;

    const float4 z0 = *(const float4*)(zr + L * 8);
    const float4 z1 = *(const float4*)(zr + L * 8 + 4);

    const unsigned cnt = g_ccnt[cidx];
    unsigned long long best = 0xFFFFFFFFFFFFFFFFull;

    if (cnt <= CAP) {
        for (unsigned i = 0; i < cnt; i++) {
            const unsigned k = g_cand[cidx * CAP + i];
            const float* er = emb + (size_t)k * DDIM;
            float4 e0 = *(const float4*)(er + L * 8);
            float4 e1 = *(const float4*)(er + L * 8 + 4);
            float d = e0.x*z0.x;
            d = fmaf(e0.y, z0.y, d); d = fmaf(e0.z, z0.z, d); d = fmaf(e0.w, z0.w, d);
            d = fmaf(e1.x, z1.x, d); d = fmaf(e1.y, z1.y, d);
            d = fmaf(e1.z, z1.z, d); d = fmaf(e1.w, z1.w, d);
#pragma unroll
            for (int off = 16; off; off >>= 1) d += __shfl_xor_sync(0xffffffffu, d, off);
            float s = fmaf(-2.f, d, g_esq[k]);
            unsigned long long pk = ((unsigned long long)orderable(s) << 32) | k;
            if (pk < best) best = pk;
        }
    } else {
        // overflow fallback: exact scan of all codes, lane-strided
        for (int k = L; k < KKE; k += 32) {
            const float* er = emb + (size_t)k * DDIM;
            float d = 0.f;
#pragma unroll 8
            for (int v = 0; v < 64; v++) {
                float4 e4 = *(const float4*)(er + v * 4);
                float4 z4 = *(const float4*)(zr + v * 4);
                d = fmaf(e4.x, z4.x, d); d = fmaf(e4.y, z4.y, d);
                d = fmaf(e4.z, z4.z, d); d = fmaf(e4.w, z4.w, d);
            }
            float s = fmaf(-2.f, d, g_esq[k]);
            unsigned long long pk = ((unsigned long long)orderable(s) << 32) | (unsigned)k;
            if (pk < best) best = pk;
        }
#pragma unroll
        for (int off = 16; off; off >>= 1) {
            unsigned long long o = __shfl_xor_sync(0xffffffffu, best, off);
            if (o < best) best = o;
        }
    }
    if (L == 0) g_minidx[cidx] = (int)(best & 0xFFFFFFFFull);
}

// ============================================================
// zero scatter buffers
// ============================================================
__global__ void zero_kernel() {
    int total = KKE * DDIM + KKE;
    for (int i = blockIdx.x * blockDim.x + threadIdx.x; i < total;
         i += gridDim.x * blockDim.x) {
        if (i < KKE * DDIM) g_zsum[i] = 0.f;
        else g_nsum[i - KKE * DDIM] = 0.f;
    }
}

// ============================================================
// gather zq -> out, scatter-add ze into z_sum / n_sum.
// Reads ze from g_zet via padded smem tile (coalesced both ways).
// ============================================================
__global__ void gs_kernel(const float* __restrict__ emb, float* __restrict__ out)
{
    __shared__ float zs[32][257];
    const int b  = blockIdx.y;
    const int n0 = blockIdx.x * 32;
    const int tx = threadIdx.x;
    const int ty = threadIdx.y;
    const int tid = ty * 32 + tx;

    // load 32 n-rows x 256 d from g_zet (coalesced)
#pragma unroll
    for (int q = 0; q < 8; q++) {
        int i = tid + 256 * q;               // 0..2047 float4 units
        int r = i >> 6, c4 = i & 63;
        float4 v = *(const float4*)&g_zet[((size_t)b * NN + n0 + r) * DDIM + c4 * 4];
        zs[r][c4 * 4 + 0] = v.x; zs[r][c4 * 4 + 1] = v.y;
        zs[r][c4 * 4 + 2] = v.z; zs[r][c4 * 4 + 3] = v.w;
    }
    __syncthreads();

    const int n = n0 + tx;
    const int idx = g_minidx[(size_t)b * NN + n];
#pragma unroll 4
    for (int d = ty; d < DDIM; d += 8) {
        float zev = zs[tx][d];
        out[((size_t)b * DDIM + d) * NN + n] = emb[(size_t)idx * DDIM + d];
        atomicAdd(&g_zsum[(size_t)idx * DDIM + d], zev);
    }
    if (ty == 0) atomicAdd(&g_nsum[idx], 1.0f);
}

// ============================================================
// EMA finalize -> tail of d_out
// ============================================================
__global__ void ema_kernel(const float* __restrict__ ema_numer,
                           const float* __restrict__ ema_denom,
                           float* __restrict__ out)
{
    const size_t OUT_OFF = (size_t)BB * DDIM * NN;
    int i = blockIdx.x * blockDim.x + threadIdx.x;
    if (i < KKE * DDIM)
        out[OUT_OFF + i] = 0.99f * ema_numer[i] + 0.01f * g_zsum[i];
    if (i < KKE)
        out[OUT_OFF + (size_t)KKE * DDIM + i] = 0.99f * ema_denom[i] + 0.01f * g_nsum[i];
}

// ============================================================
extern "C" void kernel_launch(void* const* d_in, const int* in_sizes, int n_in,
                              void* d_out, int out_size)
{
    const float* z         = (const float*)d_in[0];
    const float* W         = (const float*)d_in[1];
    const float* emb       = (const float*)d_in[2];
    const float* ema_numer = (const float*)d_in[3];
    const float* ema_denom = (const float*)d_in[4];
    float* out = (float*)d_out;
    (void)in_sizes; (void)n_in; (void)out_size;

    cudaFuncSetAttribute(argmin_approx_kernel,
                         cudaFuncAttributeMaxDynamicSharedMemorySize, SMEM_ARG);

    // 1. codebook norms + 2-plane bf16 split of emb (+ znorm2 zero)
    esq_kernel<<<(KKE * 32 + 255) / 256, 256>>>(emb);
    split_emb_kernel<<<(KKE * DDIM + 255) / 256, 256>>>(emb);

    // 2. fused GEMM1: transposed fp32/bf16 planes + znorm2
    {
        dim3 grid(NN / 128, DDIM / 64, BB);
        gemm1_kernel<<<grid, 256>>>(z, W);
    }

    // 3. Pass A: 3-term approx GEMM + candidate collection
    {
        dim3 grid(NN / 64, BB);
        argmin_approx_kernel<<<grid, 256, SMEM_ARG>>>();
    }

    // 4. Pass B: exact refinement -> g_minidx
    {
        dim3 grid(NN / 8, BB);
        refine_kernel<<<grid, 256>>>(emb);
    }

    // 5. zero scatter buffers
    zero_kernel<<<512, 256>>>();

    // 6. gather zq + scatter EMA statistics
    {
        dim3 grid(NN / 32, BB);
        dim3 blk(32, 8);
        gs_kernel<<<grid, blk>>>(emb, out);
    }

    // 7. EMA blend
    ema_kernel<<<(KKE * DDIM + 255) / 256, 256>>>(ema_numer, ema_denom, out);
}

// round 13
// speedup vs baseline: 2.2138x; 1.1292x over previous
#include <cuda_runtime.h>
#include <cuda_bf16.h>
#include <math_constants.h>
#include <cstdint>

#define BB   8
#define CIN  512
#define NN   4096
#define DDIM 256
#define KKE  2048
#define CAP  16
#define C0_BOUND 1.5e-4f

// ---- scratch (device globals; no allocation allowed) ----
__device__ float g_zet[BB * NN * DDIM];                // ze fp32 transposed [b][n][d]
__device__ float g_esq[KKE];                           // ||e_k||^2
__device__ float g_enorm[KKE];                         // ||e_k||
__device__ float g_znorm2[BB * NN];                    // ||ze_n||^2 (atomic accum)
__device__ int   g_minidx[BB * NN];                    // argmin indices
__device__ float g_zsum[KKE * DDIM];                   // segment sums
__device__ float g_nsum[KKE];                          // segment counts
__device__ __nv_bfloat16 g_embb[2u * KKE * DDIM];      // emb 2-plane bf16 split
__device__ __nv_bfloat16 g_zeb[2u * BB * NN * DDIM];   // ze 2-plane split+transposed
__device__ unsigned int g_cand[(size_t)BB * NN * CAP]; // candidate lists
__device__ unsigned int g_ccnt[BB * NN];               // candidate counts

__device__ __forceinline__ uint32_t smem_u32(const void* p) {
    uint32_t a;
    asm("{ .reg .u64 t; cvta.to.shared.u64 t, %1; cvt.u32.u64 %0, t; }" : "=r"(a) : "l"(p));
    return a;
}
__device__ __forceinline__ void ldsm_x4(uint32_t& r0, uint32_t& r1, uint32_t& r2, uint32_t& r3,
                                        uint32_t addr) {
    asm volatile("ldmatrix.sync.aligned.m8n8.x4.shared.b16 {%0,%1,%2,%3}, [%4];"
                 : "=r"(r0), "=r"(r1), "=r"(r2), "=r"(r3) : "r"(addr));
}
__device__ __forceinline__ void mma16816(float* c, const uint32_t* a, const uint32_t* b) {
    asm volatile("mma.sync.aligned.m16n8k16.row.col.f32.bf16.bf16.f32 "
                 "{%0,%1,%2,%3}, {%4,%5,%6,%7}, {%8,%9}, {%0,%1,%2,%3};"
                 : "+f"(c[0]), "+f"(c[1]), "+f"(c[2]), "+f"(c[3])
                 : "r"(a[0]), "r"(a[1]), "r"(a[2]), "r"(a[3]), "r"(b[0]), "r"(b[1]));
}
__device__ __forceinline__ uint32_t orderable(float s) {
    uint32_t u = __float_as_uint(s);
    return (u & 0x80000000u) ? ~u : (u | 0x80000000u);
}
__device__ __forceinline__ void cp_async16(uint32_t smem_addr, const void* gptr) {
    asm volatile("cp.async.cg.shared.global [%0], [%1], 16;"
                 :: "r"(smem_addr), "l"(gptr) : "memory");
}
#define CP_COMMIT() asm volatile("cp.async.commit_group;" ::: "memory")
#define CP_WAIT0()  asm volatile("cp.async.wait_group 0;" ::: "memory")

// ============================================================
// e_sq + e_norm: one warp per codebook row
// ============================================================
__global__ void esq_kernel(const float* __restrict__ emb) {
    int warp = (blockIdx.x * blockDim.x + threadIdx.x) >> 5;
    int lane = threadIdx.x & 31;
    if (warp >= KKE) return;
    const float* row = emb + (size_t)warp * DDIM;
    float s = 0.f;
#pragma unroll
    for (int i = lane; i < DDIM; i += 32) { float v = row[i]; s += v * v; }
#pragma unroll
    for (int off = 16; off; off >>= 1) s += __shfl_down_sync(0xffffffffu, s, off);
    if (lane == 0) { g_esq[warp] = s; g_enorm[warp] = sqrtf(s); }
}

// ============================================================
// 2-plane bf16 split helper
// ============================================================
__device__ __forceinline__ void split2(float x, __nv_bfloat16& h, __nv_bfloat16& m) {
    h = __float2bfloat16(x);
    m = __float2bfloat16(x - __bfloat162float(h));
}

// split emb into 2 planes; also zero g_znorm2 for this launch (graph replay)
__global__ void split_emb_kernel(const float* __restrict__ emb) {
    int i = blockIdx.x * blockDim.x + threadIdx.x;
    if (i >= KKE * DDIM) return;
    __nv_bfloat16 h, m;
    split2(emb[i], h, m);
    g_embb[i] = h;
    g_embb[(size_t)KKE * DDIM + i] = m;
    if (i < BB * NN) g_znorm2[i] = 0.f;
}

// ============================================================
// GEMM1 (fused, v2): ze = W*z -> transposed fp32 g_zet, bf16
// planes g_zeb, per-column ||ze||^2 partials.
// Block 128d x 128n, 256 threads = 16(tk d) x 16(tn n), each
// 8d x 8n (R3-proven blocking). c-chunk 16 over CIN.
// Epilogue: two 64-d halves staged through T[64][129].
// ============================================================
__global__ void __launch_bounds__(256, 2) gemm1_kernel(
    const float* __restrict__ z, const float* __restrict__ W)
{
    __shared__ float Ws[16][132];   // [c][d_local 128]
    __shared__ float Zs[16][132];   // [c][n_local 128]
    __shared__ float T[64][129];    // transpose staging (one 64-d half)

    const int n0 = blockIdx.x * 128;
    const int d0 = blockIdx.y * 128;
    const int b  = blockIdx.z;
    const int tid = threadIdx.x;
    const int tk = tid >> 4;
    const int tn = tid & 15;

    float acc[8][8];
#pragma unroll
    for (int i = 0; i < 8; i++)
#pragma unroll
        for (int j = 0; j < 8; j++) acc[i][j] = 0.f;

    for (int c0 = 0; c0 < CIN; c0 += 16) {
#pragma unroll
        for (int i = 0; i < 8; i++) {          // 128d x 16c W tile
            int lin = tid + 256 * i;
            int dl = lin >> 4, cc = lin & 15;
            Ws[cc][dl] = W[(size_t)(d0 + dl) * CIN + c0 + cc];
        }
#pragma unroll
        for (int i = 0; i < 8; i++) {          // 16c x 128n z tile
            int lin = tid + 256 * i;
            int cc = lin >> 7, nl = lin & 127;
            Zs[cc][nl] = z[((size_t)b * CIN + c0 + cc) * NN + n0 + nl];
        }
        __syncthreads();
#pragma unroll
        for (int cc = 0; cc < 16; cc++) {
            float4 a0 = *(const float4*)&Ws[cc][tk * 8];
            float4 a1 = *(const float4*)&Ws[cc][tk * 8 + 4];
            float4 b0 = *(const float4*)&Zs[cc][tn * 8];
            float4 b1 = *(const float4*)&Zs[cc][tn * 8 + 4];
            float a[8] = {a0.x, a0.y, a0.z, a0.w, a1.x, a1.y, a1.z, a1.w};
            float bv[8] = {b0.x, b0.y, b0.z, b0.w, b1.x, b1.y, b1.z, b1.w};
#pragma unroll
            for (int i = 0; i < 8; i++)
#pragma unroll
                for (int j = 0; j < 8; j++) acc[i][j] += a[i] * bv[j];
        }
        __syncthreads();
    }

    // ---- epilogue: 2 passes over 64-d halves ----
    const int nl  = tid >> 1;
    const int dof = (tid & 1) * 32;
    const size_t ZP = (size_t)BB * NN * DDIM;
    float s2tot = 0.f;

#pragma unroll 1
    for (int p = 0; p < 2; p++) {
        if (p) __syncthreads();   // pass-0 reads done before overwrite
        if ((tk >> 3) == p) {
            const int trow0 = (tk & 7) * 8;
#pragma unroll
            for (int i = 0; i < 8; i++)
#pragma unroll
                for (int j = 0; j < 8; j++)
                    T[trow0 + i][tn * 8 + j] = acc[i][j];
        }
        __syncthreads();

        const size_t base = ((size_t)b * NN + n0 + nl) * DDIM + d0 + p * 64 + dof;
        uint32_t hq[4], mq[4];
#pragma unroll
        for (int u8 = 0; u8 < 8; u8++) {
            float4 f = make_float4(T[dof + u8 * 4 + 0][nl], T[dof + u8 * 4 + 1][nl],
                                   T[dof + u8 * 4 + 2][nl], T[dof + u8 * 4 + 3][nl]);
            *(float4*)&g_zet[base + u8 * 4] = f;
            s2tot = fmaf(f.x, f.x, s2tot); s2tot = fmaf(f.y, f.y, s2tot);
            s2tot = fmaf(f.z, f.z, s2tot); s2tot = fmaf(f.w, f.w, s2tot);
            __nv_bfloat16 h0, m0, h1, m1, h2, m2, h3, m3;
            split2(f.x, h0, m0); split2(f.y, h1, m1);
            split2(f.z, h2, m2); split2(f.w, h3, m3);
            int q = (u8 & 1) * 2;
            hq[q]     = (uint32_t)__bfloat16_as_ushort(h0) | ((uint32_t)__bfloat16_as_ushort(h1) << 16);
            hq[q + 1] = (uint32_t)__bfloat16_as_ushort(h2) | ((uint32_t)__bfloat16_as_ushort(h3) << 16);
            mq[q]     = (uint32_t)__bfloat16_as_ushort(m0) | ((uint32_t)__bfloat16_as_ushort(m1) << 16);
            mq[q + 1] = (uint32_t)__bfloat16_as_ushort(m2) | ((uint32_t)__bfloat16_as_ushort(m3) << 16);
            if (u8 & 1) {
                int e0 = (u8 >> 1) * 8;
                *(uint4*)&g_zeb[base + e0]      = make_uint4(hq[0], hq[1], hq[2], hq[3]);
                *(uint4*)&g_zeb[ZP + base + e0] = make_uint4(mq[0], mq[1], mq[2], mq[3]);
            }
        }
    }
    s2tot += __shfl_xor_sync(0xffffffffu, s2tot, 1);
    if ((tid & 1) == 0)
        atomicAdd(&g_znorm2[(size_t)b * NN + n0 + nl], s2tot);
}

// ============================================================
// Pass A: 3-term approximate score GEMM (hh+hm+mh) + rigorous
// candidate collection. Double-buffered cp.async stages (A and
// B d-chunks streamed): 102 KB smem -> 2 CTAs/SM + full overlap.
// (unchanged from R12)
// ============================================================
#define STAGE_B  49152                  // A_h 16K | A_m 16K | B_h 8K | B_m 8K
#define OFF_CTRL (2 * STAGE_B)          // 98304
#define SMEM_ARG (OFF_CTRL + 6144)      // 104448

__global__ void __launch_bounds__(256, 2) argmin_approx_kernel()
{
    extern __shared__ char smem[];
    unsigned int* colthr  = (unsigned int*)(smem + OFF_CTRL);        // [64]
    unsigned int* cnt_s   = (unsigned int*)(smem + OFF_CTRL + 256);  // [64]
    float* znorm_s        = (float*)(smem + OFF_CTRL + 512);         // [64]
    float* esq_s          = (float*)(smem + OFF_CTRL + 768);         // [128]
    float* enorm_s        = (float*)(smem + OFF_CTRL + 1280);        // [128]
    unsigned int* cand_s  = (unsigned int*)(smem + OFF_CTRL + 1792); // [64*CAP]

    const int tid = threadIdx.x;
    const int wid = tid >> 5;
    const int L   = tid & 31;
    const int n0  = blockIdx.x * 64;
    const int b   = blockIdx.y;
    const int wM  = wid >> 1;        // 0..3
    const int wN  = wid & 1;         // 0..1

    const uint32_t smem_base = smem_u32(smem);
    const size_t ZP = (size_t)BB * NN * DDIM;

    if (tid < 64) {
        colthr[tid] = 0xFFFFFFFFu;
        cnt_s[tid] = 0u;
        znorm_s[tid] = sqrtf(g_znorm2[(size_t)b * NN + n0 + tid]);
    }

    // per-lane static LDSM address components (validated R6-R12)
    const int rowA_l = L & 15;
    const int kxA    = L >> 4;
    const int rowB_l = (L & 7) | ((L & 16) >> 1);
    const int kxB    = (L >> 3) & 1;

    const int PA[3] = {0, 0, 1};
    const int PB[3] = {0, 1, 0};

    auto load_stage = [&](int s) {
        const int kt = s >> 2, dch = s & 3;
        const int k0 = kt * 128;
        const uint32_t dst = smem_base + (s & 1) * STAGE_B;
#pragma unroll 4
        for (int q = 0; q < 8; q++) {          // A: 2048 granules
            int i = tid + 256 * q;
            int p = i >> 10;
            int rem = i & 1023;
            int r = rem >> 3, g = rem & 7;
            const void* src = &g_embb[((size_t)p * KKE + k0 + r) * DDIM + dch * 64 + g * 8];
            cp_async16(dst + p * 16384 + r * 128 + ((g ^ (r & 7)) * 16), src);
        }
#pragma unroll 4
        for (int q = 0; q < 4; q++) {          // B: 1024 granules
            int i = tid + 256 * q;
            int p = i >> 9;
            int rem = i & 511;
            int r = rem >> 3, g = rem & 7;
            const void* src = &g_zeb[p * ZP + ((size_t)b * NN + n0 + r) * DDIM + dch * 64 + g * 8];
            cp_async16(dst + 32768 + p * 8192 + r * 128 + ((g ^ (r & 7)) * 16), src);
        }
    };

    load_stage(0);
    CP_COMMIT();

    float acc[2][4][4];

    for (int s = 0; s < 64; s++) {
        const int kt = s >> 2, dch = s & 3;
        const int k0 = kt * 128;

        CP_WAIT0();
        __syncthreads();

        if (s + 1 < 64) { load_stage(s + 1); CP_COMMIT(); }
        if (dch == 0 && tid < 128) {
            esq_s[tid] = g_esq[k0 + tid];
            enorm_s[tid] = g_enorm[k0 + tid];
        }

        if (dch == 0) {
#pragma unroll
            for (int m = 0; m < 2; m++)
#pragma unroll
                for (int j = 0; j < 4; j++)
#pragma unroll
                    for (int r = 0; r < 4; r++) acc[m][j][r] = 0.f;
        }

        const uint32_t buf = smem_base + (s & 1) * STAGE_B;
#pragma unroll 1
        for (int t = 0; t < 3; t++) {
            const uint32_t Abase = buf + PA[t] * 16384;
            const uint32_t Bbase = buf + 32768 + PB[t] * 8192;
#pragma unroll
            for (int dc = 0; dc < 4; dc++) {
                uint32_t a[2][4], bfr[2][4];
                {
                    int rA0 = wM * 32 + rowA_l;
                    int gA  = dc * 2 + kxA;
                    ldsm_x4(a[0][0], a[0][1], a[0][2], a[0][3],
                            Abase + rA0 * 128 + ((gA ^ (rA0 & 7)) * 16));
                    int rA1 = rA0 + 16;
                    ldsm_x4(a[1][0], a[1][1], a[1][2], a[1][3],
                            Abase + rA1 * 128 + ((gA ^ (rA1 & 7)) * 16));
                    int rB0 = wN * 32 + rowB_l;
                    int gB  = dc * 2 + kxB;
                    ldsm_x4(bfr[0][0], bfr[0][1], bfr[0][2], bfr[0][3],
                            Bbase + rB0 * 128 + ((gB ^ (rB0 & 7)) * 16));
                    int rB1 = rB0 + 16;
                    ldsm_x4(bfr[1][0], bfr[1][1], bfr[1][2], bfr[1][3],
                            Bbase + rB1 * 128 + ((gB ^ (rB1 & 7)) * 16));
                }
#pragma unroll
                for (int m = 0; m < 2; m++) {
                    mma16816(acc[m][0], a[m], &bfr[0][0]);
                    mma16816(acc[m][1], a[m], &bfr[0][2]);
                    mma16816(acc[m][2], a[m], &bfr[1][0]);
                    mma16816(acc[m][3], a[m], &bfr[1][2]);
                }
            }
        }

        if (dch == 3) {
            // ---- epilogue Phase 1 ----
            float zn[8];
#pragma unroll
            for (int j = 0; j < 4; j++)
#pragma unroll
                for (int par = 0; par < 2; par++)
                    zn[j * 2 + par] = znorm_s[wN * 32 + j * 8 + (L & 3) * 2 + par];

            uint32_t umin[8];
#pragma unroll
            for (int c = 0; c < 8; c++) umin[c] = 0xFFFFFFFFu;

#pragma unroll
            for (int m = 0; m < 2; m++) {
                const int kl0 = wM * 32 + m * 16 + (L >> 2);
                const int kl1 = kl0 + 8;
                const float e0 = esq_s[kl0], e1 = esq_s[kl1];
                const float en0 = C0_BOUND * enorm_s[kl0], en1 = C0_BOUND * enorm_s[kl1];
#pragma unroll
                for (int j = 0; j < 4; j++)
#pragma unroll
                    for (int r = 0; r < 4; r++) {
                        const int kh = r >> 1, par = r & 1;
                        float sc = fmaf(-2.f, acc[m][j][r], kh ? e1 : e0);
                        acc[m][j][r] = sc;
                        float E = (kh ? en1 : en0) * zn[j * 2 + par];
                        uint32_t u = orderable(sc + E);
                        if (u < umin[j * 2 + par]) umin[j * 2 + par] = u;
                    }
            }
#pragma unroll
            for (int c = 0; c < 8; c++) {
#pragma unroll
                for (int off = 4; off <= 16; off <<= 1) {
                    uint32_t o = __shfl_xor_sync(0xffffffffu, umin[c], off);
                    if (o < umin[c]) umin[c] = o;
                }
            }
            if (L < 4) {
#pragma unroll
                for (int c = 0; c < 8; c++)
                    atomicMin(&colthr[wN * 32 + (c >> 1) * 8 + L * 2 + (c & 1)], umin[c]);
            }
            __syncthreads();

            // ---- epilogue Phase 2 ----
#pragma unroll
            for (int m = 0; m < 2; m++) {
                const int kl0 = wM * 32 + m * 16 + (L >> 2);
                const int kl1 = kl0 + 8;
                const float en0 = C0_BOUND * enorm_s[kl0], en1 = C0_BOUND * enorm_s[kl1];
#pragma unroll
                for (int j = 0; j < 4; j++)
#pragma unroll
                    for (int r = 0; r < 4; r++) {
                        const int kh = r >> 1, par = r & 1;
                        const int col = wN * 32 + j * 8 + (L & 3) * 2 + par;
                        float sc = acc[m][j][r];
                        float E = (kh ? en1 : en0) * zn[j * 2 + par];
                        if (orderable(sc - E) <= colthr[col]) {
                            unsigned pos = atomicAdd(&cnt_s[col], 1u);
                            if (pos < CAP)
                                cand_s[col * CAP + pos] = (unsigned)(k0 + (kh ? kl1 : kl0));
                        }
                    }
            }
        }
    }
    __syncthreads();
    if (tid < 64) g_ccnt[(size_t)b * NN + n0 + tid] = cnt_s[tid];
#pragma unroll
    for (int q = 0; q < 4; q++) {
        int i = tid + 256 * q;
        int lc = i >> 4, slot = i & 15;
        g_cand[((size_t)b * NN + n0 + lc) * CAP + slot] = cand_s[i];
    }
}

// ============================================================
// Pass B: exact fp32 refinement. One warp per column.
// ============================================================
__global__ void refine_kernel(const float* __restrict__ emb) {
    const int wid = threadIdx.x >> 5;
    const int L = threadIdx.x & 31;
    const int n = blockIdx.x * 8 + wid;
    const int b = blockIdx.y;
    const size_t cidx = (size_t)b * NN + n;
    const float* zr = g_zet + cidx * DDIM;

    const float4 z0 = *(const float4*)(zr + L * 8);
    const float4 z1 = *(const float4*)(zr + L * 8 + 4);

    const unsigned cnt = g_ccnt[cidx];
    unsigned long long best = 0xFFFFFFFFFFFFFFFFull;

    if (cnt <= CAP) {
        for (unsigned i = 0; i < cnt; i++) {
            const unsigned k = g_cand[cidx * CAP + i];
            const float* er = emb + (size_t)k * DDIM;
            float4 e0 = *(const float4*)(er + L * 8);
            float4 e1 = *(const float4*)(er + L * 8 + 4);
            float d = e0.x*z0.x;
            d = fmaf(e0.y, z0.y, d); d = fmaf(e0.z, z0.z, d); d = fmaf(e0.w, z0.w, d);
            d = fmaf(e1.x, z1.x, d); d = fmaf(e1.y, z1.y, d);
            d = fmaf(e1.z, z1.z, d); d = fmaf(e1.w, z1.w, d);
#pragma unroll
            for (int off = 16; off; off >>= 1) d += __shfl_xor_sync(0xffffffffu, d, off);
            float s = fmaf(-2.f, d, g_esq[k]);
            unsigned long long pk = ((unsigned long long)orderable(s) << 32) | k;
            if (pk < best) best = pk;
        }
    } else {
        for (int k = L; k < KKE; k += 32) {
            const float* er = emb + (size_t)k * DDIM;
            float d = 0.f;
#pragma unroll 8
            for (int v = 0; v < 64; v++) {
                float4 e4 = *(const float4*)(er + v * 4);
                float4 z4 = *(const float4*)(zr + v * 4);
                d = fmaf(e4.x, z4.x, d); d = fmaf(e4.y, z4.y, d);
                d = fmaf(e4.z, z4.z, d); d = fmaf(e4.w, z4.w, d);
            }
            float s = fmaf(-2.f, d, g_esq[k]);
            unsigned long long pk = ((unsigned long long)orderable(s) << 32) | (unsigned)k;
            if (pk < best) best = pk;
        }
#pragma unroll
        for (int off = 16; off; off >>= 1) {
            unsigned long long o = __shfl_xor_sync(0xffffffffu, best, off);
            if (o < best) best = o;
        }
    }
    if (L == 0) g_minidx[cidx] = (int)(best & 0xFFFFFFFFull);
}

// ============================================================
// zero scatter buffers
// ============================================================
__global__ void zero_kernel() {
    int total = KKE * DDIM + KKE;
    for (int i = blockIdx.x * blockDim.x + threadIdx.x; i < total;
         i += gridDim.x * blockDim.x) {
        if (i < KKE * DDIM) g_zsum[i] = 0.f;
        else g_nsum[i - KKE * DDIM] = 0.f;
    }
}

// ============================================================
// gather zq -> out, scatter-add ze into z_sum / n_sum.
// ============================================================
__global__ void gs_kernel(const float* __restrict__ emb, float* __restrict__ out)
{
    __shared__ float zs[32][257];
    const int b  = blockIdx.y;
    const int n0 = blockIdx.x * 32;
    const int tx = threadIdx.x;
    const int ty = threadIdx.y;
    const int tid = ty * 32 + tx;

#pragma unroll
    for (int q = 0; q < 8; q++) {
        int i = tid + 256 * q;
        int r = i >> 6, c4 = i & 63;
        float4 v = *(const float4*)&g_zet[((size_t)b * NN + n0 + r) * DDIM + c4 * 4];
        zs[r][c4 * 4 + 0] = v.x; zs[r][c4 * 4 + 1] = v.y;
        zs[r][c4 * 4 + 2] = v.z; zs[r][c4 * 4 + 3] = v.w;
    }
    __syncthreads();

    const int n = n0 + tx;
    const int idx = g_minidx[(size_t)b * NN + n];
#pragma unroll 4
    for (int d = ty; d < DDIM; d += 8) {
        float zev = zs[tx][d];
        out[((size_t)b * DDIM + d) * NN + n] = emb[(size_t)idx * DDIM + d];
        atomicAdd(&g_zsum[(size_t)idx * DDIM + d], zev);
    }
    if (ty == 0) atomicAdd(&g_nsum[idx], 1.0f);
}

// ============================================================
// EMA finalize -> tail of d_out
// ============================================================
__global__ void ema_kernel(const float* __restrict__ ema_numer,
                           const float* __restrict__ ema_denom,
                           float* __restrict__ out)
{
    const size_t OUT_OFF = (size_t)BB * DDIM * NN;
    int i = blockIdx.x * blockDim.x + threadIdx.x;
    if (i < KKE * DDIM)
        out[OUT_OFF + i] = 0.99f * ema_numer[i] + 0.01f * g_zsum[i];
    if (i < KKE)
        out[OUT_OFF + (size_t)KKE * DDIM + i] = 0.99f * ema_denom[i] + 0.01f * g_nsum[i];
}

// ============================================================
extern "C" void kernel_launch(void* const* d_in, const int* in_sizes, int n_in,
                              void* d_out, int out_size)
{
    const float* z         = (const float*)d_in[0];
    const float* W         = (const float*)d_in[1];
    const float* emb       = (const float*)d_in[2];
    const float* ema_numer = (const float*)d_in[3];
    const float* ema_denom = (const float*)d_in[4];
    float* out = (float*)d_out;
    (void)in_sizes; (void)n_in; (void)out_size;

    cudaFuncSetAttribute(argmin_approx_kernel,
                         cudaFuncAttributeMaxDynamicSharedMemorySize, SMEM_ARG);

    // 1. codebook norms + 2-plane bf16 split of emb (+ znorm2 zero)
    esq_kernel<<<(KKE * 32 + 255) / 256, 256>>>(emb);
    split_emb_kernel<<<(KKE * DDIM + 255) / 256, 256>>>(emb);

    // 2. fused GEMM1 v2 (8x8 blocking): transposed fp32/bf16 planes + znorm2
    {
        dim3 grid(NN / 128, DDIM / 128, BB);
        gemm1_kernel<<<grid, 256>>>(z, W);
    }

    // 3. Pass A: 3-term approx GEMM + candidate collection
    {
        dim3 grid(NN / 64, BB);
        argmin_approx_kernel<<<grid, 256, SMEM_ARG>>>();
    }

    // 4. Pass B: exact refinement -> g_minidx
    {
        dim3 grid(NN / 8, BB);
        refine_kernel<<<grid, 256>>>(emb);
    }

    // 5. zero scatter buffers
    zero_kernel<<<512, 256>>>();

    // 6. gather zq + scatter EMA statistics
    {
        dim3 grid(NN / 32, BB);
        dim3 blk(32, 8);
        gs_kernel<<<grid, blk>>>(emb, out);
    }

    // 7. EMA blend
    ema_kernel<<<(KKE * DDIM + 255) / 256, 256>>>(ema_numer, ema_denom, out);
}

// round 14
// speedup vs baseline: 2.3142x; 1.0453x over previous
#include <cuda_runtime.h>
#include <cuda_bf16.h>
#include <math_constants.h>
#include <cstdint>

#define BB   8
#define CIN  512
#define NN   4096
#define DDIM 256
#define KKE  2048
#define CAP  16
#define C0_BOUND 1.5e-4f

// ---- scratch (device globals; no allocation allowed) ----
__device__ float g_zet[BB * NN * DDIM];                // ze fp32 transposed [b][n][d]
__device__ float g_esq[KKE];                           // ||e_k||^2
__device__ float g_enorm[KKE];                         // ||e_k||
__device__ float g_znorm2[BB * NN];                    // ||ze_n||^2 (atomic accum)
__device__ int   g_minidx[BB * NN];                    // argmin indices
__device__ float g_zsum[KKE * DDIM];                   // segment sums
__device__ float g_nsum[KKE];                          // segment counts
__device__ __nv_bfloat16 g_embb[2u * KKE * DDIM];      // emb 2-plane bf16 split
__device__ __nv_bfloat16 g_zeb[2u * BB * NN * DDIM];   // ze 2-plane split+transposed
__device__ unsigned int g_cand[(size_t)BB * NN * CAP]; // candidate lists
__device__ unsigned int g_ccnt[BB * NN];               // candidate counts

__device__ __forceinline__ uint32_t smem_u32(const void* p) {
    uint32_t a;
    asm("{ .reg .u64 t; cvta.to.shared.u64 t, %1; cvt.u32.u64 %0, t; }" : "=r"(a) : "l"(p));
    return a;
}
__device__ __forceinline__ void ldsm_x4(uint32_t& r0, uint32_t& r1, uint32_t& r2, uint32_t& r3,
                                        uint32_t addr) {
    asm volatile("ldmatrix.sync.aligned.m8n8.x4.shared.b16 {%0,%1,%2,%3}, [%4];"
                 : "=r"(r0), "=r"(r1), "=r"(r2), "=r"(r3) : "r"(addr));
}
__device__ __forceinline__ void mma16816(float* c, const uint32_t* a, const uint32_t* b) {
    asm volatile("mma.sync.aligned.m16n8k16.row.col.f32.bf16.bf16.f32 "
                 "{%0,%1,%2,%3}, {%4,%5,%6,%7}, {%8,%9}, {%0,%1,%2,%3};"
                 : "+f"(c[0]), "+f"(c[1]), "+f"(c[2]), "+f"(c[3])
                 : "r"(a[0]), "r"(a[1]), "r"(a[2]), "r"(a[3]), "r"(b[0]), "r"(b[1]));
}
__device__ __forceinline__ uint32_t orderable(float s) {
    uint32_t u = __float_as_uint(s);
    return (u & 0x80000000u) ? ~u : (u | 0x80000000u);
}
__device__ __forceinline__ void cp_async16(uint32_t smem_addr, const void* gptr) {
    asm volatile("cp.async.cg.shared.global [%0], [%1], 16;"
                 :: "r"(smem_addr), "l"(gptr) : "memory");
}
#define CP_COMMIT() asm volatile("cp.async.commit_group;" ::: "memory")
#define CP_WAIT0()  asm volatile("cp.async.wait_group 0;" ::: "memory")

// ============================================================
// 2-plane bf16 split helper
// ============================================================
__device__ __forceinline__ void split2(float x, __nv_bfloat16& h, __nv_bfloat16& m) {
    h = __float2bfloat16(x);
    m = __float2bfloat16(x - __bfloat162float(h));
}

// ============================================================
// prep: fused esq/enorm + emb 2-plane split + zero all scatter
// buffers. One warp per codebook row; 65536 threads total.
// ============================================================
__global__ void __launch_bounds__(256) prep_kernel(const float* __restrict__ emb) {
    const int tid = blockIdx.x * blockDim.x + threadIdx.x;   // 0..65535
    const int gw = tid >> 5;                                 // 0..2047 (code row)
    const int lane = threadIdx.x & 31;

    const float* row = emb + (size_t)gw * DDIM + lane * 8;
    float4 v0 = *(const float4*)row;
    float4 v1 = *(const float4*)(row + 4);
    float s = v0.x*v0.x + v0.y*v0.y + v0.z*v0.z + v0.w*v0.w
            + v1.x*v1.x + v1.y*v1.y + v1.z*v1.z + v1.w*v1.w;

    // split the 8 values into h/m planes, packed as uint4
    float vals[8] = {v0.x, v0.y, v0.z, v0.w, v1.x, v1.y, v1.z, v1.w};
    uint32_t hq[4], mq[4];
#pragma unroll
    for (int p2 = 0; p2 < 4; p2++) {
        __nv_bfloat16 h0, m0, h1, m1;
        split2(vals[p2 * 2], h0, m0);
        split2(vals[p2 * 2 + 1], h1, m1);
        hq[p2] = (uint32_t)__bfloat16_as_ushort(h0) | ((uint32_t)__bfloat16_as_ushort(h1) << 16);
        mq[p2] = (uint32_t)__bfloat16_as_ushort(m0) | ((uint32_t)__bfloat16_as_ushort(m1) << 16);
    }
    const size_t eoff = (size_t)gw * DDIM + lane * 8;
    *(uint4*)&g_embb[eoff] = make_uint4(hq[0], hq[1], hq[2], hq[3]);
    *(uint4*)&g_embb[(size_t)KKE * DDIM + eoff] = make_uint4(mq[0], mq[1], mq[2], mq[3]);

#pragma unroll
    for (int off = 16; off; off >>= 1) s += __shfl_down_sync(0xffffffffu, s, off);
    if (lane == 0) { g_esq[gw] = s; g_enorm[gw] = sqrtf(s); }

    // ---- zero scatter buffers (graph replay requires re-zeroing) ----
    const float4 z4 = make_float4(0.f, 0.f, 0.f, 0.f);
    ((float4*)g_zsum)[tid] = z4;
    ((float4*)g_zsum)[tid + 65536] = z4;
    if (tid < 8192) ((float4*)g_znorm2)[tid] = z4;
    if (tid < 512)  ((float4*)g_nsum)[tid] = z4;
}

// ============================================================
// GEMM1 (fused): ze = W*z -> transposed fp32 g_zet, bf16
// planes g_zeb, per-column ||ze||^2 partials.
// Block 128d x 128n, 256 threads, 8d x 8n each (R13 version).
// ============================================================
__global__ void __launch_bounds__(256, 2) gemm1_kernel(
    const float* __restrict__ z, const float* __restrict__ W)
{
    __shared__ float Ws[16][132];
    __shared__ float Zs[16][132];
    __shared__ float T[64][129];

    const int n0 = blockIdx.x * 128;
    const int d0 = blockIdx.y * 128;
    const int b  = blockIdx.z;
    const int tid = threadIdx.x;
    const int tk = tid >> 4;
    const int tn = tid & 15;

    float acc[8][8];
#pragma unroll
    for (int i = 0; i < 8; i++)
#pragma unroll
        for (int j = 0; j < 8; j++) acc[i][j] = 0.f;

    for (int c0 = 0; c0 < CIN; c0 += 16) {
#pragma unroll
        for (int i = 0; i < 8; i++) {
            int lin = tid + 256 * i;
            int dl = lin >> 4, cc = lin & 15;
            Ws[cc][dl] = W[(size_t)(d0 + dl) * CIN + c0 + cc];
        }
#pragma unroll
        for (int i = 0; i < 8; i++) {
            int lin = tid + 256 * i;
            int cc = lin >> 7, nl = lin & 127;
            Zs[cc][nl] = z[((size_t)b * CIN + c0 + cc) * NN + n0 + nl];
        }
        __syncthreads();
#pragma unroll
        for (int cc = 0; cc < 16; cc++) {
            float4 a0 = *(const float4*)&Ws[cc][tk * 8];
            float4 a1 = *(const float4*)&Ws[cc][tk * 8 + 4];
            float4 b0 = *(const float4*)&Zs[cc][tn * 8];
            float4 b1 = *(const float4*)&Zs[cc][tn * 8 + 4];
            float a[8] = {a0.x, a0.y, a0.z, a0.w, a1.x, a1.y, a1.z, a1.w};
            float bv[8] = {b0.x, b0.y, b0.z, b0.w, b1.x, b1.y, b1.z, b1.w};
#pragma unroll
            for (int i = 0; i < 8; i++)
#pragma unroll
                for (int j = 0; j < 8; j++) acc[i][j] += a[i] * bv[j];
        }
        __syncthreads();
    }

    // ---- epilogue: 2 passes over 64-d halves ----
    const int nl  = tid >> 1;
    const int dof = (tid & 1) * 32;
    const size_t ZP = (size_t)BB * NN * DDIM;
    float s2tot = 0.f;

#pragma unroll 1
    for (int p = 0; p < 2; p++) {
        if (p) __syncthreads();
        if ((tk >> 3) == p) {
            const int trow0 = (tk & 7) * 8;
#pragma unroll
            for (int i = 0; i < 8; i++)
#pragma unroll
                for (int j = 0; j < 8; j++)
                    T[trow0 + i][tn * 8 + j] = acc[i][j];
        }
        __syncthreads();

        const size_t base = ((size_t)b * NN + n0 + nl) * DDIM + d0 + p * 64 + dof;
        uint32_t hq[4], mq[4];
#pragma unroll
        for (int u8 = 0; u8 < 8; u8++) {
            float4 f = make_float4(T[dof + u8 * 4 + 0][nl], T[dof + u8 * 4 + 1][nl],
                                   T[dof + u8 * 4 + 2][nl], T[dof + u8 * 4 + 3][nl]);
            *(float4*)&g_zet[base + u8 * 4] = f;
            s2tot = fmaf(f.x, f.x, s2tot); s2tot = fmaf(f.y, f.y, s2tot);
            s2tot = fmaf(f.z, f.z, s2tot); s2tot = fmaf(f.w, f.w, s2tot);
            __nv_bfloat16 h0, m0, h1, m1, h2, m2, h3, m3;
            split2(f.x, h0, m0); split2(f.y, h1, m1);
            split2(f.z, h2, m2); split2(f.w, h3, m3);
            int q = (u8 & 1) * 2;
            hq[q]     = (uint32_t)__bfloat16_as_ushort(h0) | ((uint32_t)__bfloat16_as_ushort(h1) << 16);
            hq[q + 1] = (uint32_t)__bfloat16_as_ushort(h2) | ((uint32_t)__bfloat16_as_ushort(h3) << 16);
            mq[q]     = (uint32_t)__bfloat16_as_ushort(m0) | ((uint32_t)__bfloat16_as_ushort(m1) << 16);
            mq[q + 1] = (uint32_t)__bfloat16_as_ushort(m2) | ((uint32_t)__bfloat16_as_ushort(m3) << 16);
            if (u8 & 1) {
                int e0 = (u8 >> 1) * 8;
                *(uint4*)&g_zeb[base + e0]      = make_uint4(hq[0], hq[1], hq[2], hq[3]);
                *(uint4*)&g_zeb[ZP + base + e0] = make_uint4(mq[0], mq[1], mq[2], mq[3]);
            }
        }
    }
    s2tot += __shfl_xor_sync(0xffffffffu, s2tot, 1);
    if ((tid & 1) == 0)
        atomicAdd(&g_znorm2[(size_t)b * NN + n0 + nl], s2tot);
}

// ============================================================
// Pass A: 3-term approximate score GEMM + candidate collection.
// v4: per-granule fragment dedup (aH/aM/bH/bM loaded ONCE, used
// across hh/hm/mh terms): 48 -> 32 LDSM per stage.
// Double-buffered cp.async A+B stages, 102 KB smem, 2 CTAs/SM.
// ============================================================
#define STAGE_B  49152                  // A_h 16K | A_m 16K | B_h 8K | B_m 8K
#define OFF_CTRL (2 * STAGE_B)          // 98304
#define SMEM_ARG (OFF_CTRL + 6144)      // 104448

__global__ void __launch_bounds__(256, 2) argmin_approx_kernel()
{
    extern __shared__ char smem[];
    unsigned int* colthr  = (unsigned int*)(smem + OFF_CTRL);        // [64]
    unsigned int* cnt_s   = (unsigned int*)(smem + OFF_CTRL + 256);  // [64]
    float* znorm_s        = (float*)(smem + OFF_CTRL + 512);         // [64]
    float* esq_s          = (float*)(smem + OFF_CTRL + 768);         // [128]
    float* enorm_s        = (float*)(smem + OFF_CTRL + 1280);        // [128]
    unsigned int* cand_s  = (unsigned int*)(smem + OFF_CTRL + 1792); // [64*CAP]

    const int tid = threadIdx.x;
    const int wid = tid >> 5;
    const int L   = tid & 31;
    const int n0  = blockIdx.x * 64;
    const int b   = blockIdx.y;
    const int wM  = wid >> 1;        // 0..3
    const int wN  = wid & 1;         // 0..1

    const uint32_t smem_base = smem_u32(smem);
    const size_t ZP = (size_t)BB * NN * DDIM;

    if (tid < 64) {
        colthr[tid] = 0xFFFFFFFFu;
        cnt_s[tid] = 0u;
        znorm_s[tid] = sqrtf(g_znorm2[(size_t)b * NN + n0 + tid]);
    }

    const int rowA_l = L & 15;
    const int kxA    = L >> 4;
    const int rowB_l = (L & 7) | ((L & 16) >> 1);
    const int kxB    = (L >> 3) & 1;

    auto load_stage = [&](int s) {
        const int kt = s >> 2, dch = s & 3;
        const int k0 = kt * 128;
        const uint32_t dst = smem_base + (s & 1) * STAGE_B;
#pragma unroll 4
        for (int q = 0; q < 8; q++) {          // A: 2048 granules
            int i = tid + 256 * q;
            int p = i >> 10;
            int rem = i & 1023;
            int r = rem >> 3, g = rem & 7;
            const void* src = &g_embb[((size_t)p * KKE + k0 + r) * DDIM + dch * 64 + g * 8];
            cp_async16(dst + p * 16384 + r * 128 + ((g ^ (r & 7)) * 16), src);
        }
#pragma unroll 4
        for (int q = 0; q < 4; q++) {          // B: 1024 granules
            int i = tid + 256 * q;
            int p = i >> 9;
            int rem = i & 511;
            int r = rem >> 3, g = rem & 7;
            const void* src = &g_zeb[p * ZP + ((size_t)b * NN + n0 + r) * DDIM + dch * 64 + g * 8];
            cp_async16(dst + 32768 + p * 8192 + r * 128 + ((g ^ (r & 7)) * 16), src);
        }
    };

    load_stage(0);
    CP_COMMIT();

    float acc[2][4][4];

    for (int s = 0; s < 64; s++) {
        const int kt = s >> 2, dch = s & 3;
        const int k0 = kt * 128;

        CP_WAIT0();
        __syncthreads();

        if (s + 1 < 64) { load_stage(s + 1); CP_COMMIT(); }
        if (dch == 0 && tid < 128) {
            esq_s[tid] = g_esq[k0 + tid];
            enorm_s[tid] = g_enorm[k0 + tid];
        }

        if (dch == 0) {
#pragma unroll
            for (int m = 0; m < 2; m++)
#pragma unroll
                for (int j = 0; j < 4; j++)
#pragma unroll
                    for (int r = 0; r < 4; r++) acc[m][j][r] = 0.f;
        }

        const uint32_t buf = smem_base + (s & 1) * STAGE_B;
#pragma unroll
        for (int dc = 0; dc < 4; dc++) {
            uint32_t aH[2][4], aM[2][4], bH[2][4], bM[2][4];
            {
                const int rA0 = wM * 32 + rowA_l;
                const int rA1 = rA0 + 16;
                const int gA  = dc * 2 + kxA;
                const uint32_t swA0 = ((gA ^ (rA0 & 7)) * 16);
                const uint32_t swA1 = ((gA ^ (rA1 & 7)) * 16);
                ldsm_x4(aH[0][0], aH[0][1], aH[0][2], aH[0][3], buf + rA0 * 128 + swA0);
                ldsm_x4(aH[1][0], aH[1][1], aH[1][2], aH[1][3], buf + rA1 * 128 + swA1);
                ldsm_x4(aM[0][0], aM[0][1], aM[0][2], aM[0][3], buf + 16384 + rA0 * 128 + swA0);
                ldsm_x4(aM[1][0], aM[1][1], aM[1][2], aM[1][3], buf + 16384 + rA1 * 128 + swA1);
                const int rB0 = wN * 32 + rowB_l;
                const int rB1 = rB0 + 16;
                const int gB  = dc * 2 + kxB;
                const uint32_t swB0 = ((gB ^ (rB0 & 7)) * 16);
                const uint32_t swB1 = ((gB ^ (rB1 & 7)) * 16);
                ldsm_x4(bH[0][0], bH[0][1], bH[0][2], bH[0][3], buf + 32768 + rB0 * 128 + swB0);
                ldsm_x4(bH[1][0], bH[1][1], bH[1][2], bH[1][3], buf + 32768 + rB1 * 128 + swB1);
                ldsm_x4(bM[0][0], bM[0][1], bM[0][2], bM[0][3], buf + 40960 + rB0 * 128 + swB0);
                ldsm_x4(bM[1][0], bM[1][1], bM[1][2], bM[1][3], buf + 40960 + rB1 * 128 + swB1);
            }
#pragma unroll
            for (int m = 0; m < 2; m++) {      // term hh
                mma16816(acc[m][0], aH[m], &bH[0][0]);
                mma16816(acc[m][1], aH[m], &bH[0][2]);
                mma16816(acc[m][2], aH[m], &bH[1][0]);
                mma16816(acc[m][3], aH[m], &bH[1][2]);
            }
#pragma unroll
            for (int m = 0; m < 2; m++) {      // term hm
                mma16816(acc[m][0], aH[m], &bM[0][0]);
                mma16816(acc[m][1], aH[m], &bM[0][2]);
                mma16816(acc[m][2], aH[m], &bM[1][0]);
                mma16816(acc[m][3], aH[m], &bM[1][2]);
            }
#pragma unroll
            for (int m = 0; m < 2; m++) {      // term mh
                mma16816(acc[m][0], aM[m], &bH[0][0]);
                mma16816(acc[m][1], aM[m], &bH[0][2]);
                mma16816(acc[m][2], aM[m], &bH[1][0]);
                mma16816(acc[m][3], aM[m], &bH[1][2]);
            }
        }

        if (dch == 3) {
            // ---- epilogue Phase 1 ----
            float zn[8];
#pragma unroll
            for (int j = 0; j < 4; j++)
#pragma unroll
                for (int par = 0; par < 2; par++)
                    zn[j * 2 + par] = znorm_s[wN * 32 + j * 8 + (L & 3) * 2 + par];

            uint32_t umin[8];
#pragma unroll
            for (int c = 0; c < 8; c++) umin[c] = 0xFFFFFFFFu;

#pragma unroll
            for (int m = 0; m < 2; m++) {
                const int kl0 = wM * 32 + m * 16 + (L >> 2);
                const int kl1 = kl0 + 8;
                const float e0 = esq_s[kl0], e1 = esq_s[kl1];
                const float en0 = C0_BOUND * enorm_s[kl0], en1 = C0_BOUND * enorm_s[kl1];
#pragma unroll
                for (int j = 0; j < 4; j++)
#pragma unroll
                    for (int r = 0; r < 4; r++) {
                        const int kh = r >> 1, par = r & 1;
                        float sc = fmaf(-2.f, acc[m][j][r], kh ? e1 : e0);
                        acc[m][j][r] = sc;
                        float E = (kh ? en1 : en0) * zn[j * 2 + par];
                        uint32_t u = orderable(sc + E);
                        if (u < umin[j * 2 + par]) umin[j * 2 + par] = u;
                    }
            }
#pragma unroll
            for (int c = 0; c < 8; c++) {
#pragma unroll
                for (int off = 4; off <= 16; off <<= 1) {
                    uint32_t o = __shfl_xor_sync(0xffffffffu, umin[c], off);
                    if (o < umin[c]) umin[c] = o;
                }
            }
            if (L < 4) {
#pragma unroll
                for (int c = 0; c < 8; c++)
                    atomicMin(&colthr[wN * 32 + (c >> 1) * 8 + L * 2 + (c & 1)], umin[c]);
            }
            __syncthreads();

            // ---- epilogue Phase 2 ----
#pragma unroll
            for (int m = 0; m < 2; m++) {
                const int kl0 = wM * 32 + m * 16 + (L >> 2);
                const int kl1 = kl0 + 8;
                const float en0 = C0_BOUND * enorm_s[kl0], en1 = C0_BOUND * enorm_s[kl1];
#pragma unroll
                for (int j = 0; j < 4; j++)
#pragma unroll
                    for (int r = 0; r < 4; r++) {
                        const int kh = r >> 1, par = r & 1;
                        const int col = wN * 32 + j * 8 + (L & 3) * 2 + par;
                        float sc = acc[m][j][r];
                        float E = (kh ? en1 : en0) * zn[j * 2 + par];
                        if (orderable(sc - E) <= colthr[col]) {
                            unsigned pos = atomicAdd(&cnt_s[col], 1u);
                            if (pos < CAP)
                                cand_s[col * CAP + pos] = (unsigned)(k0 + (kh ? kl1 : kl0));
                        }
                    }
            }
        }
    }
    __syncthreads();
    if (tid < 64) g_ccnt[(size_t)b * NN + n0 + tid] = cnt_s[tid];
#pragma unroll
    for (int q = 0; q < 4; q++) {
        int i = tid + 256 * q;
        int lc = i >> 4, slot = i & 15;
        g_cand[((size_t)b * NN + n0 + lc) * CAP + slot] = cand_s[i];
    }
}

// ============================================================
// Pass B: exact fp32 refinement. One warp per column.
// ============================================================
__global__ void refine_kernel(const float* __restrict__ emb) {
    const int wid = threadIdx.x >> 5;
    const int L = threadIdx.x & 31;
    const int n = blockIdx.x * 8 + wid;
    const int b = blockIdx.y;
    const size_t cidx = (size_t)b * NN + n;
    const float* zr = g_zet + cidx * DDIM;

    const float4 z0 = *(const float4*)(zr + L * 8);
    const float4 z1 = *(const float4*)(zr + L * 8 + 4);

    const unsigned cnt = g_ccnt[cidx];
    unsigned long long best = 0xFFFFFFFFFFFFFFFFull;

    if (cnt <= CAP) {
        for (unsigned i = 0; i < cnt; i++) {
            const unsigned k = g_cand[cidx * CAP + i];
            const float* er = emb + (size_t)k * DDIM;
            float4 e0 = *(const float4*)(er + L * 8);
            float4 e1 = *(const float4*)(er + L * 8 + 4);
            float d = e0.x*z0.x;
            d = fmaf(e0.y, z0.y, d); d = fmaf(e0.z, z0.z, d); d = fmaf(e0.w, z0.w, d);
            d = fmaf(e1.x, z1.x, d); d = fmaf(e1.y, z1.y, d);
            d = fmaf(e1.z, z1.z, d); d = fmaf(e1.w, z1.w, d);
#pragma unroll
            for (int off = 16; off; off >>= 1) d += __shfl_xor_sync(0xffffffffu, d, off);
            float s = fmaf(-2.f, d, g_esq[k]);
            unsigned long long pk = ((unsigned long long)orderable(s) << 32) | k;
            if (pk < best) best = pk;
        }
    } else {
        for (int k = L; k < KKE; k += 32) {
            const float* er = emb + (size_t)k * DDIM;
            float d = 0.f;
#pragma unroll 8
            for (int v = 0; v < 64; v++) {
                float4 e4 = *(const float4*)(er + v * 4);
                float4 z4 = *(const float4*)(zr + v * 4);
                d = fmaf(e4.x, z4.x, d); d = fmaf(e4.y, z4.y, d);
                d = fmaf(e4.z, z4.z, d); d = fmaf(e4.w, z4.w, d);
            }
            float s = fmaf(-2.f, d, g_esq[k]);
            unsigned long long pk = ((unsigned long long)orderable(s) << 32) | (unsigned)k;
            if (pk < best) best = pk;
        }
#pragma unroll
        for (int off = 16; off; off >>= 1) {
            unsigned long long o = __shfl_xor_sync(0xffffffffu, best, off);
            if (o < best) best = o;
        }
    }
    if (L == 0) g_minidx[cidx] = (int)(best & 0xFFFFFFFFull);
}

// ============================================================
// gather zq -> out, scatter-add ze into z_sum / n_sum.
// ============================================================
__global__ void gs_kernel(const float* __restrict__ emb, float* __restrict__ out)
{
    __shared__ float zs[32][257];
    const int b  = blockIdx.y;
    const int n0 = blockIdx.x * 32;
    const int tx = threadIdx.x;
    const int ty = threadIdx.y;
    const int tid = ty * 32 + tx;

#pragma unroll
    for (int q = 0; q < 8; q++) {
        int i = tid + 256 * q;
        int r = i >> 6, c4 = i & 63;
        float4 v = *(const float4*)&g_zet[((size_t)b * NN + n0 + r) * DDIM + c4 * 4];
        zs[r][c4 * 4 + 0] = v.x; zs[r][c4 * 4 + 1] = v.y;
        zs[r][c4 * 4 + 2] = v.z; zs[r][c4 * 4 + 3] = v.w;
    }
    __syncthreads();

    const int n = n0 + tx;
    const int idx = g_minidx[(size_t)b * NN + n];
#pragma unroll 4
    for (int d = ty; d < DDIM; d += 8) {
        float zev = zs[tx][d];
        out[((size_t)b * DDIM + d) * NN + n] = emb[(size_t)idx * DDIM + d];
        atomicAdd(&g_zsum[(size_t)idx * DDIM + d], zev);
    }
    if (ty == 0) atomicAdd(&g_nsum[idx], 1.0f);
}

// ============================================================
// EMA finalize -> tail of d_out
// ============================================================
__global__ void ema_kernel(const float* __restrict__ ema_numer,
                           const float* __restrict__ ema_denom,
                           float* __restrict__ out)
{
    const size_t OUT_OFF = (size_t)BB * DDIM * NN;
    int i = blockIdx.x * blockDim.x + threadIdx.x;
    if (i < KKE * DDIM)
        out[OUT_OFF + i] = 0.99f * ema_numer[i] + 0.01f * g_zsum[i];
    if (i < KKE)
        out[OUT_OFF + (size_t)KKE * DDIM + i] = 0.99f * ema_denom[i] + 0.01f * g_nsum[i];
}

// ============================================================
extern "C" void kernel_launch(void* const* d_in, const int* in_sizes, int n_in,
                              void* d_out, int out_size)
{
    const float* z         = (const float*)d_in[0];
    const float* W         = (const float*)d_in[1];
    const float* emb       = (const float*)d_in[2];
    const float* ema_numer = (const float*)d_in[3];
    const float* ema_denom = (const float*)d_in[4];
    float* out = (float*)d_out;
    (void)in_sizes; (void)n_in; (void)out_size;

    cudaFuncSetAttribute(argmin_approx_kernel,
                         cudaFuncAttributeMaxDynamicSharedMemorySize, SMEM_ARG);

    // 1. fused prep: esq/enorm + emb split + zero scatter buffers
    prep_kernel<<<256, 256>>>(emb);

    // 2. fused GEMM1 (8x8): transposed fp32/bf16 planes + znorm2
    {
        dim3 grid(NN / 128, DDIM / 128, BB);
        gemm1_kernel<<<grid, 256>>>(z, W);
    }

    // 3. Pass A: 3-term approx GEMM + candidate collection
    {
        dim3 grid(NN / 64, BB);
        argmin_approx_kernel<<<grid, 256, SMEM_ARG>>>();
    }

    // 4. Pass B: exact refinement -> g_minidx
    {
        dim3 grid(NN / 8, BB);
        refine_kernel<<<grid, 256>>>(emb);
    }

    // 5. gather zq + scatter EMA statistics
    {
        dim3 grid(NN / 32, BB);
        dim3 blk(32, 8);
        gs_kernel<<<grid, blk>>>(emb, out);
    }

    // 6. EMA blend
    ema_kernel<<<(KKE * DDIM + 255) / 256, 256>>>(ema_numer, ema_denom, out);
}